// round 2
// baseline (speedup 1.0000x reference)
#include <cuda_runtime.h>
#include <cuda_bf16.h>
#include <math.h>

#define S_LEN 4096
#define D_MOD 768
#define N_HEAD 12
#define DH 64
#define N_LAYER 4
#define FF_DIM 3072
#define CHUNK 256
#define WIN 256

// ---------------- scratch (device globals; no allocation) ----------------
__device__ float g_x [S_LEN * D_MOD];
__device__ float g_q [S_LEN * D_MOD];
__device__ float g_k [S_LEN * D_MOD];
__device__ float g_v [S_LEN * D_MOD];
__device__ float g_a [S_LEN * D_MOD];
__device__ float g_o [S_LEN * D_MOD];
__device__ float g_ff[S_LEN * FF_DIM];
__device__ float g_pooled[D_MOD];
__device__ float g_h1[512];
__device__ float g_h2[256];
__device__ float g_msum[1];

// ---------------- embedding ----------------
__global__ void embed_kernel(const int* __restrict__ ids,
                             const float* __restrict__ wemb,
                             const float* __restrict__ pemb,
                             float* __restrict__ X)
{
    int row = blockIdx.x;
    int id  = ids[row];
    const float* wp = wemb + (size_t)id * D_MOD;
    const float* pp = pemb + (size_t)row * D_MOD;
    float* xp = X + (size_t)row * D_MOD;
    for (int d = threadIdx.x; d < D_MOD; d += blockDim.x)
        xp[d] = wp[d] + pp[d];
}

// ---------------- LayerNorm (optionally with residual add), in-place on X ----
__global__ void __launch_bounds__(256) ln_kernel(float* __restrict__ X,
                                                 const float* __restrict__ Aadd,
                                                 const float* __restrict__ g,
                                                 const float* __restrict__ b)
{
    int row = blockIdx.x;
    int tid = threadIdx.x;
    __shared__ float red[256];
    float vals[3];
    float s = 0.f;
    const size_t base = (size_t)row * D_MOD;
#pragma unroll
    for (int i = 0; i < 3; i++) {
        int d = tid + i * 256;
        float v = X[base + d];
        if (Aadd) v += Aadd[base + d];
        vals[i] = v;
        s += v;
    }
    red[tid] = s; __syncthreads();
    for (int o = 128; o > 0; o >>= 1) { if (tid < o) red[tid] += red[tid + o]; __syncthreads(); }
    float mean = red[0] * (1.0f / D_MOD);
    __syncthreads();
    float ss = 0.f;
#pragma unroll
    for (int i = 0; i < 3; i++) { float dv = vals[i] - mean; ss += dv * dv; }
    red[tid] = ss; __syncthreads();
    for (int o = 128; o > 0; o >>= 1) { if (tid < o) red[tid] += red[tid + o]; __syncthreads(); }
    float rstd = rsqrtf(red[0] * (1.0f / D_MOD) + 1e-5f);
#pragma unroll
    for (int i = 0; i < 3; i++) {
        int d = tid + i * 256;
        X[base + d] = (vals[i] - mean) * rstd * g[d] + b[d];
    }
}

// ---------------- SGEMM 128x128x8, fp32, fused epilogue ----------------
// EPI: 0 = bias, 1 = bias then *0.125 (Q scale), 2 = bias then exact GELU
template<int EPI>
__global__ void __launch_bounds__(256) sgemm_kernel(const float* __restrict__ A,
                                                    const float* __restrict__ B,
                                                    const float* __restrict__ bias,
                                                    float* __restrict__ C,
                                                    int M, int N, int K)
{
    __shared__ float As[8][128];
    __shared__ float Bs[8][128];
    int tid = threadIdx.x;
    int m0 = blockIdx.y * 128;
    int n0 = blockIdx.x * 128;
    int tx = tid & 15, ty = tid >> 4;

    float acc[8][8];
#pragma unroll
    for (int i = 0; i < 8; i++)
#pragma unroll
        for (int j = 0; j < 8; j++) acc[i][j] = 0.f;

    int a_row = tid >> 1;
    int a_k4  = (tid & 1) * 4;
    int b_k   = tid >> 5;
    int b_n4  = (tid & 31) * 4;

    const float* Aptr = A + (size_t)(m0 + a_row) * K + a_k4;
    const float* Bptr = B + (size_t)b_k * N + n0 + b_n4;

    for (int k0 = 0; k0 < K; k0 += 8) {
        float4 av = *(const float4*)(Aptr + k0);
        As[a_k4 + 0][a_row] = av.x;
        As[a_k4 + 1][a_row] = av.y;
        As[a_k4 + 2][a_row] = av.z;
        As[a_k4 + 3][a_row] = av.w;
        *(float4*)&Bs[b_k][b_n4] = *(const float4*)(Bptr + (size_t)k0 * N);
        __syncthreads();
#pragma unroll
        for (int kk = 0; kk < 8; kk++) {
            float a_frag[8], b_frag[8];
#pragma unroll
            for (int i = 0; i < 8; i++) a_frag[i] = As[kk][ty * 8 + i];
#pragma unroll
            for (int j = 0; j < 8; j++) b_frag[j] = Bs[kk][tx * 8 + j];
#pragma unroll
            for (int i = 0; i < 8; i++)
#pragma unroll
                for (int j = 0; j < 8; j++)
                    acc[i][j] += a_frag[i] * b_frag[j];
        }
        __syncthreads();
    }

#pragma unroll
    for (int i = 0; i < 8; i++) {
        int row = m0 + ty * 8 + i;
#pragma unroll
        for (int j = 0; j < 8; j++) {
            int col = n0 + tx * 8 + j;
            float v = acc[i][j] + bias[col];
            if (EPI == 1) v *= 0.125f;
            if (EPI == 2) v = 0.5f * v * (1.0f + erff(v * 0.70710678118654752f));
            C[(size_t)row * N + col] = v;
        }
    }
}

// ---------------- band attention (flash-style online softmax) ----------------
__global__ void __launch_bounds__(256) attn_kernel(const float* __restrict__ Q,
                                                   const float* __restrict__ K,
                                                   const float* __restrict__ V,
                                                   const int* __restrict__ mask,
                                                   float* __restrict__ O)
{
    int n  = blockIdx.x;   // chunk 0..15
    int h  = blockIdx.y;   // head 0..11
    int qi = threadIdx.x;  // query row in chunk
    int sq = n * CHUNK + qi;

    __shared__ float ks[64][64];
    __shared__ float vs[64][64];

    float qreg[64];
    const float* qp = Q + (size_t)sq * D_MOD + h * DH;
#pragma unroll
    for (int d = 0; d < 64; d++) qreg[d] = qp[d];

    float m = -1e30f, l = 0.f;
    float acc[64];
#pragma unroll
    for (int d = 0; d < 64; d++) acc[d] = 0.f;

    int lo = sq - WIN; if (lo < 0) lo = 0;
    int hi = sq + WIN; if (hi > S_LEN - 1) hi = S_LEN - 1;
    int base = n * CHUNK - CHUNK;
    // block-uniform union of key range
    int blo = base;            if (blo < 0) blo = 0;
    int bhi = base + 3 * CHUNK - 1 + WIN - WIN; // [base, base+767]
    bhi = base + 767;          if (bhi > S_LEN - 1) bhi = S_LEN - 1;

    for (int t = 0; t < 12; t++) {
        int tstart = base + t * 64;
        if (tstart + 63 < blo || tstart > bhi) continue;   // block-uniform skip
        __syncthreads();
        for (int e = threadIdx.x; e < 64 * 64; e += 256) {
            int jj = e >> 6, d = e & 63;
            int g2 = tstart + jj;
            float kv = 0.f, vv = 0.f;
            if (g2 >= 0 && g2 < S_LEN) {
                size_t off = (size_t)g2 * D_MOD + h * DH + d;
                kv = K[off];
                vv = V[off];
            }
            ks[jj][d] = kv;
            vs[jj][d] = vv;
        }
        __syncthreads();
        int j0 = lo - tstart; if (j0 < 0) j0 = 0;
        int j1 = hi - tstart; if (j1 > 63) j1 = 63;
        for (int jj = j0; jj <= j1; jj++) {
            int g2 = tstart + jj;
            if (mask[g2] == 0) continue;
            float s = 0.f;
#pragma unroll
            for (int d = 0; d < 64; d++) s += qreg[d] * ks[jj][d];
            if (s <= m) {
                float p = __expf(s - m);
                l += p;
#pragma unroll
                for (int d = 0; d < 64; d++) acc[d] += p * vs[jj][d];
            } else {
                float sc = __expf(m - s);
                l = l * sc + 1.0f;
#pragma unroll
                for (int d = 0; d < 64; d++) acc[d] = acc[d] * sc + vs[jj][d];
                m = s;
            }
        }
    }
    float inv = 1.0f / l;
    float* op = O + (size_t)sq * D_MOD + h * DH;
#pragma unroll
    for (int d = 0; d < 64; d++) op[d] = acc[d] * inv;
}

// ---------------- pooling + head ----------------
__global__ void zero_pooled_kernel(float* __restrict__ pooled)
{
    for (int d = threadIdx.x; d < D_MOD; d += blockDim.x) pooled[d] = 0.f;
}

__global__ void msum_kernel(const int* __restrict__ mask, float* __restrict__ out)
{
    __shared__ float red[256];
    int tid = threadIdx.x;
    float s = 0.f;
    for (int i = tid; i < S_LEN; i += 256) s += (float)mask[i];
    red[tid] = s; __syncthreads();
    for (int o = 128; o > 0; o >>= 1) { if (tid < o) red[tid] += red[tid + o]; __syncthreads(); }
    if (tid == 0) out[0] = fmaxf(red[0], 1e-9f);
}

__global__ void __launch_bounds__(256) pool_kernel(const float* __restrict__ X,
                                                   const int* __restrict__ mask,
                                                   float* __restrict__ pooled)
{
    int s0 = blockIdx.x * 256;
    int tid = threadIdx.x;
    float a0 = 0.f, a1 = 0.f, a2 = 0.f;
    for (int r = 0; r < 256; r++) {
        float mf = (float)mask[s0 + r];
        const float* xp = X + (size_t)(s0 + r) * D_MOD;
        a0 += xp[tid]       * mf;
        a1 += xp[tid + 256] * mf;
        a2 += xp[tid + 512] * mf;
    }
    atomicAdd(&pooled[tid],       a0);
    atomicAdd(&pooled[tid + 256], a1);
    atomicAdd(&pooled[tid + 512], a2);
}

__global__ void head1_kernel(const float* __restrict__ pooled,
                             const float* __restrict__ W1, const float* __restrict__ b1,
                             const float* __restrict__ msum, float* __restrict__ h1)
{
    int i = threadIdx.x;   // 512 threads
    float inv = 1.0f / msum[0];
    float dot = 0.f;
    for (int d = 0; d < D_MOD; d++) dot += pooled[d] * W1[(size_t)d * 512 + i];
    h1[i] = fmaxf(dot * inv + b1[i], 0.f);
}

__global__ void head2_kernel(const float* __restrict__ h1,
                             const float* __restrict__ W2, const float* __restrict__ b2,
                             float* __restrict__ h2)
{
    int i = threadIdx.x;   // 256 threads
    if (i < 250) {
        float dot = 0.f;
        for (int d = 0; d < 512; d++) dot += h1[d] * W2[(size_t)d * 250 + i];
        h2[i] = fmaxf(dot + b2[i], 0.f);
    } else if (i < 256) {
        h2[i] = 0.f;
    }
}

__global__ void head3_kernel(const float* __restrict__ h2,
                             const float* __restrict__ W3, const float* __restrict__ b3,
                             float* __restrict__ out, int out_size)
{
    __shared__ float red[256];
    __shared__ float pred;
    int tid = threadIdx.x;
    float v = (tid < 250) ? h2[tid] * W3[tid] : 0.f;
    red[tid] = v; __syncthreads();
    for (int o = 128; o > 0; o >>= 1) { if (tid < o) red[tid] += red[tid + o]; __syncthreads(); }
    if (tid == 0) pred = red[0] + b3[0];
    __syncthreads();
    for (int i = tid; i < out_size; i += 256) out[i] = pred;
}

// ---------------- launch ----------------
extern "C" void kernel_launch(void* const* d_in, const int* in_sizes, int n_in,
                              void* d_out, int out_size)
{
    const int*   ids    = (const int*)  d_in[0];
    const int*   mask   = (const int*)  d_in[1];
    const float* wemb   = (const float*)d_in[2];
    const float* pemb   = (const float*)d_in[3];
    const float* emb_g  = (const float*)d_in[4];
    const float* emb_b  = (const float*)d_in[5];
    const float* Wq     = (const float*)d_in[6];
    const float* Wk     = (const float*)d_in[7];
    const float* Wv     = (const float*)d_in[8];
    const float* Wo     = (const float*)d_in[9];
    const float* bq     = (const float*)d_in[10];
    const float* bk     = (const float*)d_in[11];
    const float* bv     = (const float*)d_in[12];
    const float* bo     = (const float*)d_in[13];
    const float* ln1_g  = (const float*)d_in[14];
    const float* ln1_b  = (const float*)d_in[15];
    const float* Wff1   = (const float*)d_in[16];
    const float* bff1   = (const float*)d_in[17];
    const float* Wff2   = (const float*)d_in[18];
    const float* bff2   = (const float*)d_in[19];
    const float* ln2_g  = (const float*)d_in[20];
    const float* ln2_b  = (const float*)d_in[21];
    const float* W1     = (const float*)d_in[22];
    const float* b1     = (const float*)d_in[23];
    const float* W2     = (const float*)d_in[24];
    const float* b2     = (const float*)d_in[25];
    const float* W3     = (const float*)d_in[26];
    const float* b3     = (const float*)d_in[27];
    float* out = (float*)d_out;

    float *x, *q, *k, *v, *a, *o, *ff, *pooled, *h1, *h2, *msum;
    cudaGetSymbolAddress((void**)&x,      g_x);
    cudaGetSymbolAddress((void**)&q,      g_q);
    cudaGetSymbolAddress((void**)&k,      g_k);
    cudaGetSymbolAddress((void**)&v,      g_v);
    cudaGetSymbolAddress((void**)&a,      g_a);
    cudaGetSymbolAddress((void**)&o,      g_o);
    cudaGetSymbolAddress((void**)&ff,     g_ff);
    cudaGetSymbolAddress((void**)&pooled, g_pooled);
    cudaGetSymbolAddress((void**)&h1,     g_h1);
    cudaGetSymbolAddress((void**)&h2,     g_h2);
    cudaGetSymbolAddress((void**)&msum,   g_msum);

    dim3 gemm_blk(256);
    dim3 g768 (D_MOD / 128, S_LEN / 128);   // (6, 32)
    dim3 g3072(FF_DIM / 128, S_LEN / 128);  // (24, 32)

    embed_kernel<<<S_LEN, 256>>>(ids, wemb, pemb, x);
    ln_kernel<<<S_LEN, 256>>>(x, nullptr, emb_g, emb_b);

    for (int l = 0; l < N_LAYER; l++) {
        const float* Wq_l  = Wq  + (size_t)l * D_MOD * D_MOD;
        const float* Wk_l  = Wk  + (size_t)l * D_MOD * D_MOD;
        const float* Wv_l  = Wv  + (size_t)l * D_MOD * D_MOD;
        const float* Wo_l  = Wo  + (size_t)l * D_MOD * D_MOD;
        const float* Wf1_l = Wff1 + (size_t)l * D_MOD * FF_DIM;
        const float* Wf2_l = Wff2 + (size_t)l * FF_DIM * D_MOD;

        sgemm_kernel<1><<<g768, gemm_blk>>>(x, Wq_l, bq + l * D_MOD, q, S_LEN, D_MOD, D_MOD);
        sgemm_kernel<0><<<g768, gemm_blk>>>(x, Wk_l, bk + l * D_MOD, k, S_LEN, D_MOD, D_MOD);
        sgemm_kernel<0><<<g768, gemm_blk>>>(x, Wv_l, bv + l * D_MOD, v, S_LEN, D_MOD, D_MOD);

        attn_kernel<<<dim3(S_LEN / CHUNK, N_HEAD), 256>>>(q, k, v, mask, a);

        sgemm_kernel<0><<<g768, gemm_blk>>>(a, Wo_l, bo + l * D_MOD, o, S_LEN, D_MOD, D_MOD);
        ln_kernel<<<S_LEN, 256>>>(x, o, ln1_g + l * D_MOD, ln1_b + l * D_MOD);

        sgemm_kernel<2><<<g3072, gemm_blk>>>(x, Wf1_l, bff1 + l * FF_DIM, ff, S_LEN, FF_DIM, D_MOD);
        sgemm_kernel<0><<<g768,  gemm_blk>>>(ff, Wf2_l, bff2 + l * D_MOD, o, S_LEN, D_MOD, FF_DIM);
        ln_kernel<<<S_LEN, 256>>>(x, o, ln2_g + l * D_MOD, ln2_b + l * D_MOD);
    }

    zero_pooled_kernel<<<1, 256>>>(pooled);
    msum_kernel<<<1, 256>>>(mask, msum);
    pool_kernel<<<S_LEN / 256, 256>>>(x, mask, pooled);
    head1_kernel<<<1, 512>>>(pooled, W1, b1, msum, h1);
    head2_kernel<<<1, 256>>>(h1, W2, b2, h2);
    head3_kernel<<<1, 256>>>(h2, W3, b3, out, out_size);
}

// round 5
// speedup vs baseline: 1.6976x; 1.6976x over previous
#include <cuda_runtime.h>
#include <cuda_bf16.h>
#include <math.h>
#include <stdint.h>

#define S_LEN 4096
#define D_MOD 768
#define N_HEAD 12
#define DH 64
#define N_LAYER 4
#define FF_DIM 3072
#define CHUNK 256
#define WIN 256

// ---------------- scratch (device globals; no allocation) ----------------
__device__ float g_x [S_LEN * D_MOD];
__device__ float g_q [S_LEN * D_MOD];
__device__ float g_k [S_LEN * D_MOD];
__device__ float g_v [S_LEN * D_MOD];
__device__ float g_a [S_LEN * D_MOD];
__device__ float g_o [S_LEN * D_MOD];
__device__ float g_ff[S_LEN * FF_DIM];
__device__ float g_pooled[D_MOD];
__device__ float g_h1[512];
__device__ float g_h2[256];
__device__ float g_msum[1];
// transposed weights [N][K] per layer
__device__ float g_WqT [N_LAYER * D_MOD * D_MOD];
__device__ float g_WkT [N_LAYER * D_MOD * D_MOD];
__device__ float g_WvT [N_LAYER * D_MOD * D_MOD];
__device__ float g_WoT [N_LAYER * D_MOD * D_MOD];
__device__ float g_Wf1T[N_LAYER * D_MOD * FF_DIM];
__device__ float g_Wf2T[N_LAYER * FF_DIM * D_MOD];

__device__ __forceinline__ float to_tf32(float x) {
    float r; asm("cvt.rna.tf32.f32 %0, %1;" : "=f"(r) : "f"(x)); return r;
}

__device__ __forceinline__ void mma_tf32(float* d, const uint32_t* a, const uint32_t* b) {
    asm volatile(
        "mma.sync.aligned.m16n8k8.row.col.f32.tf32.tf32.f32 "
        "{%0,%1,%2,%3}, {%4,%5,%6,%7}, {%8,%9}, {%0,%1,%2,%3};\n"
        : "+f"(d[0]), "+f"(d[1]), "+f"(d[2]), "+f"(d[3])
        : "r"(a[0]), "r"(a[1]), "r"(a[2]), "r"(a[3]), "r"(b[0]), "r"(b[1]));
}

// ---------------- weight transpose: W[K][N] -> Wt[N][K], per-layer via blockIdx.z
__global__ void transpose_kernel(const float* __restrict__ W, float* __restrict__ Wt,
                                 int K, int N)
{
    __shared__ float t[32][33];
    size_t lo = (size_t)blockIdx.z * K * N;
    const float* Wl = W + lo;
    float* Wtl = Wt + lo;
    int k0 = blockIdx.y * 32, n0 = blockIdx.x * 32;
    int tx = threadIdx.x, ty = threadIdx.y;
#pragma unroll
    for (int i = 0; i < 32; i += 8)
        t[ty + i][tx] = Wl[(size_t)(k0 + ty + i) * N + n0 + tx];
    __syncthreads();
#pragma unroll
    for (int i = 0; i < 32; i += 8)
        Wtl[(size_t)(n0 + ty + i) * K + k0 + tx] = t[tx][ty + i];
}

// ---------------- tf32 mma.sync GEMM: C[M,N] = A[M,K] @ Bt[N,K]^T + bias -------
// EPI: 0 = bias, 1 = bias then *0.125 (Q scale), 2 = bias then exact GELU
// BM=BN=128, BK=32, 8 warps, warp tile 64x32 (4x4 m16n8k8 fragments)
#define PAD_LD 36
#define BUF_FLOATS (128 * PAD_LD)
#define TG_SMEM_BYTES (4 * BUF_FLOATS * 4)

template<int EPI>
__global__ void __launch_bounds__(256) tgemm_kernel(const float* __restrict__ A,
                                                    const float* __restrict__ Bt,
                                                    const float* __restrict__ bias,
                                                    float* __restrict__ C,
                                                    int M, int N, int K)
{
    extern __shared__ float sm[];
    float* sA = sm;                      // [2][128][36]
    float* sB = sm + 2 * BUF_FLOATS;     // [2][128][36]

    const int tid  = threadIdx.x;
    const int wid  = tid >> 5;
    const int lane = tid & 31;
    const int wm   = wid & 1;            // 0..1  -> m offset wm*64
    const int wn   = wid >> 1;           // 0..3  -> n offset wn*32
    const int g    = lane >> 2;          // group id 0..7
    const int cq   = lane & 3;           // 0..3
    const int m0 = blockIdx.y * 128;
    const int n0 = blockIdx.x * 128;
    const int NC = K >> 5;

    const float* Ab = A  + (size_t)m0 * K;
    const float* Bb = Bt + (size_t)n0 * K;

    float acc[4][4][4];
#pragma unroll
    for (int i = 0; i < 4; i++)
#pragma unroll
        for (int j = 0; j < 4; j++)
#pragma unroll
            for (int r = 0; r < 4; r++) acc[i][j][r] = 0.f;

    const int lrow = tid >> 3;           // 0..31 (rows i*32+lrow)
    const int lkq  = (tid & 7) * 4;      // 0..28 step 4

    // ---- load chunk 0 into buffer 0
#pragma unroll
    for (int i = 0; i < 4; i++) {
        int row = lrow + i * 32;
        float4 va = *(const float4*)(Ab + (size_t)row * K + lkq);
        float4 vb = *(const float4*)(Bb + (size_t)row * K + lkq);
        va.x = to_tf32(va.x); va.y = to_tf32(va.y); va.z = to_tf32(va.z); va.w = to_tf32(va.w);
        vb.x = to_tf32(vb.x); vb.y = to_tf32(vb.y); vb.z = to_tf32(vb.z); vb.w = to_tf32(vb.w);
        *(float4*)(sA + row * PAD_LD + lkq) = va;
        *(float4*)(sB + row * PAD_LD + lkq) = vb;
    }
    __syncthreads();

    for (int c = 0; c < NC; c++) {
        const int buf = c & 1;
        float4 ra[4], rb[4];
        const bool more = (c + 1 < NC);
        if (more) {
            const int k0 = (c + 1) << 5;
#pragma unroll
            for (int i = 0; i < 4; i++) {
                int row = lrow + i * 32;
                ra[i] = *(const float4*)(Ab + (size_t)row * K + k0 + lkq);
                rb[i] = *(const float4*)(Bb + (size_t)row * K + k0 + lkq);
            }
        }

        const float* cA = sA + buf * BUF_FLOATS;
        const float* cB = sB + buf * BUF_FLOATS;
#pragma unroll
        for (int kk = 0; kk < 4; kk++) {
            const int kb = kk * 8;
            uint32_t af[4][4], bf[4][2];
#pragma unroll
            for (int mt = 0; mt < 4; mt++) {
                int r = wm * 64 + mt * 16 + g;
                af[mt][0] = __float_as_uint(cA[(size_t)r       * PAD_LD + kb + cq]);
                af[mt][1] = __float_as_uint(cA[(size_t)(r + 8) * PAD_LD + kb + cq]);
                af[mt][2] = __float_as_uint(cA[(size_t)r       * PAD_LD + kb + cq + 4]);
                af[mt][3] = __float_as_uint(cA[(size_t)(r + 8) * PAD_LD + kb + cq + 4]);
            }
#pragma unroll
            for (int nt = 0; nt < 4; nt++) {
                int nrow = wn * 32 + nt * 8 + g;
                bf[nt][0] = __float_as_uint(cB[(size_t)nrow * PAD_LD + kb + cq]);
                bf[nt][1] = __float_as_uint(cB[(size_t)nrow * PAD_LD + kb + cq + 4]);
            }
#pragma unroll
            for (int mt = 0; mt < 4; mt++)
#pragma unroll
                for (int nt = 0; nt < 4; nt++)
                    mma_tf32(acc[mt][nt], af[mt], bf[nt]);
        }

        if (more) {
            const int nb = (c + 1) & 1;
            float* dA = sA + nb * BUF_FLOATS;
            float* dB = sB + nb * BUF_FLOATS;
#pragma unroll
            for (int i = 0; i < 4; i++) {
                int row = lrow + i * 32;
                float4 va = ra[i], vb = rb[i];
                va.x = to_tf32(va.x); va.y = to_tf32(va.y); va.z = to_tf32(va.z); va.w = to_tf32(va.w);
                vb.x = to_tf32(vb.x); vb.y = to_tf32(vb.y); vb.z = to_tf32(vb.z); vb.w = to_tf32(vb.w);
                *(float4*)(dA + row * PAD_LD + lkq) = va;
                *(float4*)(dB + row * PAD_LD + lkq) = vb;
            }
        }
        __syncthreads();
    }

    // ---- epilogue: bias + EPI, write float2 pairs
#pragma unroll
    for (int mt = 0; mt < 4; mt++) {
        int row = m0 + wm * 64 + mt * 16 + g;
#pragma unroll
        for (int nt = 0; nt < 4; nt++) {
            int col = n0 + wn * 32 + nt * 8 + 2 * cq;
            float bb0 = bias[col], bb1 = bias[col + 1];
            float v0 = acc[mt][nt][0] + bb0;
            float v1 = acc[mt][nt][1] + bb1;
            float v2 = acc[mt][nt][2] + bb0;
            float v3 = acc[mt][nt][3] + bb1;
            if (EPI == 1) { v0 *= 0.125f; v1 *= 0.125f; v2 *= 0.125f; v3 *= 0.125f; }
            if (EPI == 2) {
                v0 = 0.5f * v0 * (1.0f + erff(v0 * 0.70710678118654752f));
                v1 = 0.5f * v1 * (1.0f + erff(v1 * 0.70710678118654752f));
                v2 = 0.5f * v2 * (1.0f + erff(v2 * 0.70710678118654752f));
                v3 = 0.5f * v3 * (1.0f + erff(v3 * 0.70710678118654752f));
            }
            *(float2*)(C + (size_t)row * N + col)       = make_float2(v0, v1);
            *(float2*)(C + (size_t)(row + 8) * N + col) = make_float2(v2, v3);
        }
    }
}

// ---------------- embedding ----------------
__global__ void embed_kernel(const int* __restrict__ ids,
                             const float* __restrict__ wemb,
                             const float* __restrict__ pemb,
                             float* __restrict__ X)
{
    int row = blockIdx.x;
    int id  = ids[row];
    const float* wp = wemb + (size_t)id * D_MOD;
    const float* pp = pemb + (size_t)row * D_MOD;
    float* xp = X + (size_t)row * D_MOD;
    for (int d = threadIdx.x; d < D_MOD; d += blockDim.x)
        xp[d] = wp[d] + pp[d];
}

// ---------------- LayerNorm (optionally with residual add), in-place on X ----
__global__ void __launch_bounds__(256) ln_kernel(float* __restrict__ X,
                                                 const float* __restrict__ Aadd,
                                                 const float* __restrict__ g,
                                                 const float* __restrict__ b)
{
    int row = blockIdx.x;
    int tid = threadIdx.x;
    __shared__ float red[256];
    float vals[3];
    float s = 0.f;
    const size_t base = (size_t)row * D_MOD;
#pragma unroll
    for (int i = 0; i < 3; i++) {
        int d = tid + i * 256;
        float v = X[base + d];
        if (Aadd) v += Aadd[base + d];
        vals[i] = v;
        s += v;
    }
    red[tid] = s; __syncthreads();
    for (int o = 128; o > 0; o >>= 1) { if (tid < o) red[tid] += red[tid + o]; __syncthreads(); }
    float mean = red[0] * (1.0f / D_MOD);
    __syncthreads();
    float ss = 0.f;
#pragma unroll
    for (int i = 0; i < 3; i++) { float dv = vals[i] - mean; ss += dv * dv; }
    red[tid] = ss; __syncthreads();
    for (int o = 128; o > 0; o >>= 1) { if (tid < o) red[tid] += red[tid + o]; __syncthreads(); }
    float rstd = rsqrtf(red[0] * (1.0f / D_MOD) + 1e-5f);
#pragma unroll
    for (int i = 0; i < 3; i++) {
        int d = tid + i * 256;
        X[base + d] = (vals[i] - mean) * rstd * g[d] + b[d];
    }
}

// ---------------- band attention (flash-style online softmax) ----------------
__global__ void __launch_bounds__(256) attn_kernel(const float* __restrict__ Q,
                                                   const float* __restrict__ K,
                                                   const float* __restrict__ V,
                                                   const int* __restrict__ mask,
                                                   float* __restrict__ O)
{
    int n  = blockIdx.x;   // chunk 0..15
    int h  = blockIdx.y;   // head 0..11
    int qi = threadIdx.x;  // query row in chunk
    int sq = n * CHUNK + qi;

    __shared__ float ks[64][64];
    __shared__ float vs[64][64];

    float qreg[64];
    const float* qp = Q + (size_t)sq * D_MOD + h * DH;
#pragma unroll
    for (int d = 0; d < 64; d++) qreg[d] = qp[d];

    float m = -1e30f, l = 0.f;
    float acc[64];
#pragma unroll
    for (int d = 0; d < 64; d++) acc[d] = 0.f;

    int lo = sq - WIN; if (lo < 0) lo = 0;
    int hi = sq + WIN; if (hi > S_LEN - 1) hi = S_LEN - 1;
    int base = n * CHUNK - CHUNK;
    int blo = base;            if (blo < 0) blo = 0;
    int bhi = base + 767;      if (bhi > S_LEN - 1) bhi = S_LEN - 1;

    for (int t = 0; t < 12; t++) {
        int tstart = base + t * 64;
        if (tstart + 63 < blo || tstart > bhi) continue;
        __syncthreads();
        for (int e = threadIdx.x; e < 64 * 64; e += 256) {
            int jj = e >> 6, d = e & 63;
            int g2 = tstart + jj;
            float kv = 0.f, vv = 0.f;
            if (g2 >= 0 && g2 < S_LEN) {
                size_t off = (size_t)g2 * D_MOD + h * DH + d;
                kv = K[off];
                vv = V[off];
            }
            ks[jj][d] = kv;
            vs[jj][d] = vv;
        }
        __syncthreads();
        int j0 = lo - tstart; if (j0 < 0) j0 = 0;
        int j1 = hi - tstart; if (j1 > 63) j1 = 63;
        for (int jj = j0; jj <= j1; jj++) {
            int g2 = tstart + jj;
            if (mask[g2] == 0) continue;
            float s = 0.f;
#pragma unroll
            for (int d = 0; d < 64; d++) s += qreg[d] * ks[jj][d];
            if (s <= m) {
                float p = __expf(s - m);
                l += p;
#pragma unroll
                for (int d = 0; d < 64; d++) acc[d] += p * vs[jj][d];
            } else {
                float sc = __expf(m - s);
                l = l * sc + 1.0f;
#pragma unroll
                for (int d = 0; d < 64; d++) acc[d] = acc[d] * sc + vs[jj][d];
                m = s;
            }
        }
    }
    float inv = 1.0f / l;
    float* op = O + (size_t)sq * D_MOD + h * DH;
#pragma unroll
    for (int d = 0; d < 64; d++) op[d] = acc[d] * inv;
}

// ---------------- pooling + head ----------------
__global__ void zero_pooled_kernel(float* __restrict__ pooled)
{
    for (int d = threadIdx.x; d < D_MOD; d += blockDim.x) pooled[d] = 0.f;
}

__global__ void msum_kernel(const int* __restrict__ mask, float* __restrict__ out)
{
    __shared__ float red[256];
    int tid = threadIdx.x;
    float s = 0.f;
    for (int i = tid; i < S_LEN; i += 256) s += (float)mask[i];
    red[tid] = s; __syncthreads();
    for (int o = 128; o > 0; o >>= 1) { if (tid < o) red[tid] += red[tid + o]; __syncthreads(); }
    if (tid == 0) out[0] = fmaxf(red[0], 1e-9f);
}

__global__ void __launch_bounds__(256) pool_kernel(const float* __restrict__ X,
                                                   const int* __restrict__ mask,
                                                   float* __restrict__ pooled)
{
    int s0 = blockIdx.x * 256;
    int tid = threadIdx.x;
    float a0 = 0.f, a1 = 0.f, a2 = 0.f;
    for (int r = 0; r < 256; r++) {
        float mf = (float)mask[s0 + r];
        const float* xp = X + (size_t)(s0 + r) * D_MOD;
        a0 += xp[tid]       * mf;
        a1 += xp[tid + 256] * mf;
        a2 += xp[tid + 512] * mf;
    }
    atomicAdd(&pooled[tid],       a0);
    atomicAdd(&pooled[tid + 256], a1);
    atomicAdd(&pooled[tid + 512], a2);
}

__global__ void head1_kernel(const float* __restrict__ pooled,
                             const float* __restrict__ W1, const float* __restrict__ b1,
                             const float* __restrict__ msum, float* __restrict__ h1)
{
    int i = threadIdx.x;   // 512 threads
    float inv = 1.0f / msum[0];
    float dot = 0.f;
    for (int d = 0; d < D_MOD; d++) dot += pooled[d] * W1[(size_t)d * 512 + i];
    h1[i] = fmaxf(dot * inv + b1[i], 0.f);
}

__global__ void head2_kernel(const float* __restrict__ h1,
                             const float* __restrict__ W2, const float* __restrict__ b2,
                             float* __restrict__ h2)
{
    int i = threadIdx.x;   // 256 threads
    if (i < 250) {
        float dot = 0.f;
        for (int d = 0; d < 512; d++) dot += h1[d] * W2[(size_t)d * 250 + i];
        h2[i] = fmaxf(dot + b2[i], 0.f);
    } else if (i < 256) {
        h2[i] = 0.f;
    }
}

__global__ void head3_kernel(const float* __restrict__ h2,
                             const float* __restrict__ W3, const float* __restrict__ b3,
                             float* __restrict__ out, int out_size)
{
    __shared__ float red[256];
    __shared__ float pred;
    int tid = threadIdx.x;
    float v = (tid < 250) ? h2[tid] * W3[tid] : 0.f;
    red[tid] = v; __syncthreads();
    for (int o = 128; o > 0; o >>= 1) { if (tid < o) red[tid] += red[tid + o]; __syncthreads(); }
    if (tid == 0) pred = red[0] + b3[0];
    __syncthreads();
    for (int i = tid; i < out_size; i += 256) out[i] = pred;
}

// ---------------- launch ----------------
extern "C" void kernel_launch(void* const* d_in, const int* in_sizes, int n_in,
                              void* d_out, int out_size)
{
    const int*   ids    = (const int*)  d_in[0];
    const int*   mask   = (const int*)  d_in[1];
    const float* wemb   = (const float*)d_in[2];
    const float* pemb   = (const float*)d_in[3];
    const float* emb_g  = (const float*)d_in[4];
    const float* emb_b  = (const float*)d_in[5];
    const float* Wq     = (const float*)d_in[6];
    const float* Wk     = (const float*)d_in[7];
    const float* Wv     = (const float*)d_in[8];
    const float* Wo     = (const float*)d_in[9];
    const float* bq     = (const float*)d_in[10];
    const float* bk     = (const float*)d_in[11];
    const float* bv     = (const float*)d_in[12];
    const float* bo     = (const float*)d_in[13];
    const float* ln1_g  = (const float*)d_in[14];
    const float* ln1_b  = (const float*)d_in[15];
    const float* Wff1   = (const float*)d_in[16];
    const float* bff1   = (const float*)d_in[17];
    const float* Wff2   = (const float*)d_in[18];
    const float* bff2   = (const float*)d_in[19];
    const float* ln2_g  = (const float*)d_in[20];
    const float* ln2_b  = (const float*)d_in[21];
    const float* W1     = (const float*)d_in[22];
    const float* b1     = (const float*)d_in[23];
    const float* W2     = (const float*)d_in[24];
    const float* b2     = (const float*)d_in[25];
    const float* W3     = (const float*)d_in[26];
    const float* b3     = (const float*)d_in[27];
    float* out = (float*)d_out;

    float *x, *q, *k, *v, *a, *o, *ff, *pooled, *h1, *h2, *msum;
    float *WqT, *WkT, *WvT, *WoT, *Wf1T, *Wf2T;
    cudaGetSymbolAddress((void**)&x,      g_x);
    cudaGetSymbolAddress((void**)&q,      g_q);
    cudaGetSymbolAddress((void**)&k,      g_k);
    cudaGetSymbolAddress((void**)&v,      g_v);
    cudaGetSymbolAddress((void**)&a,      g_a);
    cudaGetSymbolAddress((void**)&o,      g_o);
    cudaGetSymbolAddress((void**)&ff,     g_ff);
    cudaGetSymbolAddress((void**)&pooled, g_pooled);
    cudaGetSymbolAddress((void**)&h1,     g_h1);
    cudaGetSymbolAddress((void**)&h2,     g_h2);
    cudaGetSymbolAddress((void**)&msum,   g_msum);
    cudaGetSymbolAddress((void**)&WqT,    g_WqT);
    cudaGetSymbolAddress((void**)&WkT,    g_WkT);
    cudaGetSymbolAddress((void**)&WvT,    g_WvT);
    cudaGetSymbolAddress((void**)&WoT,    g_WoT);
    cudaGetSymbolAddress((void**)&Wf1T,   g_Wf1T);
    cudaGetSymbolAddress((void**)&Wf2T,   g_Wf2T);

    static bool attr_set = false;
    if (!attr_set) {
        cudaFuncSetAttribute(tgemm_kernel<0>, cudaFuncAttributeMaxDynamicSharedMemorySize, TG_SMEM_BYTES);
        cudaFuncSetAttribute(tgemm_kernel<1>, cudaFuncAttributeMaxDynamicSharedMemorySize, TG_SMEM_BYTES);
        cudaFuncSetAttribute(tgemm_kernel<2>, cudaFuncAttributeMaxDynamicSharedMemorySize, TG_SMEM_BYTES);
        attr_set = true;
    }

    // transpose weights: W[K][N] -> Wt[N][K]
    {
        dim3 tb(32, 8);
        transpose_kernel<<<dim3(D_MOD/32, D_MOD/32, N_LAYER), tb>>>(Wq,   WqT,  D_MOD, D_MOD);
        transpose_kernel<<<dim3(D_MOD/32, D_MOD/32, N_LAYER), tb>>>(Wk,   WkT,  D_MOD, D_MOD);
        transpose_kernel<<<dim3(D_MOD/32, D_MOD/32, N_LAYER), tb>>>(Wv,   WvT,  D_MOD, D_MOD);
        transpose_kernel<<<dim3(D_MOD/32, D_MOD/32, N_LAYER), tb>>>(Wo,   WoT,  D_MOD, D_MOD);
        transpose_kernel<<<dim3(FF_DIM/32, D_MOD/32, N_LAYER), tb>>>(Wff1, Wf1T, D_MOD, FF_DIM);
        transpose_kernel<<<dim3(D_MOD/32, FF_DIM/32, N_LAYER), tb>>>(Wff2, Wf2T, FF_DIM, D_MOD);
    }

    dim3 tg768 (D_MOD / 128, S_LEN / 128);   // (6, 32)
    dim3 tg3072(FF_DIM / 128, S_LEN / 128);  // (24, 32)

    embed_kernel<<<S_LEN, 256>>>(ids, wemb, pemb, x);
    ln_kernel<<<S_LEN, 256>>>(x, nullptr, emb_g, emb_b);

    for (int l = 0; l < N_LAYER; l++) {
        const float* WqT_l  = WqT  + (size_t)l * D_MOD * D_MOD;
        const float* WkT_l  = WkT  + (size_t)l * D_MOD * D_MOD;
        const float* WvT_l  = WvT  + (size_t)l * D_MOD * D_MOD;
        const float* WoT_l  = WoT  + (size_t)l * D_MOD * D_MOD;
        const float* Wf1T_l = Wf1T + (size_t)l * D_MOD * FF_DIM;
        const float* Wf2T_l = Wf2T + (size_t)l * FF_DIM * D_MOD;

        tgemm_kernel<1><<<tg768, 256, TG_SMEM_BYTES>>>(x, WqT_l, bq + l * D_MOD, q, S_LEN, D_MOD, D_MOD);
        tgemm_kernel<0><<<tg768, 256, TG_SMEM_BYTES>>>(x, WkT_l, bk + l * D_MOD, k, S_LEN, D_MOD, D_MOD);
        tgemm_kernel<0><<<tg768, 256, TG_SMEM_BYTES>>>(x, WvT_l, bv + l * D_MOD, v, S_LEN, D_MOD, D_MOD);

        attn_kernel<<<dim3(S_LEN / CHUNK, N_HEAD), 256>>>(q, k, v, mask, a);

        tgemm_kernel<0><<<tg768, 256, TG_SMEM_BYTES>>>(a, WoT_l, bo + l * D_MOD, o, S_LEN, D_MOD, D_MOD);
        ln_kernel<<<S_LEN, 256>>>(x, o, ln1_g + l * D_MOD, ln1_b + l * D_MOD);

        tgemm_kernel<2><<<tg3072, 256, TG_SMEM_BYTES>>>(x, Wf1T_l, bff1 + l * FF_DIM, ff, S_LEN, FF_DIM, D_MOD);
        tgemm_kernel<0><<<tg768,  256, TG_SMEM_BYTES>>>(ff, Wf2T_l, bff2 + l * D_MOD, o, S_LEN, D_MOD, FF_DIM);
        ln_kernel<<<S_LEN, 256>>>(x, o, ln2_g + l * D_MOD, ln2_b + l * D_MOD);
    }

    zero_pooled_kernel<<<1, 256>>>(pooled);
    msum_kernel<<<1, 256>>>(mask, msum);
    pool_kernel<<<S_LEN / 256, 256>>>(x, mask, pooled);
    head1_kernel<<<1, 512>>>(pooled, W1, b1, msum, h1);
    head2_kernel<<<1, 256>>>(h1, W2, b2, h2);
    head3_kernel<<<1, 256>>>(h2, W3, b3, out, out_size);
}

// round 9
// speedup vs baseline: 1.9397x; 1.1426x over previous
#include <cuda_runtime.h>
#include <cuda_bf16.h>
#include <math.h>
#include <stdint.h>

#define S_LEN 4096
#define D_MOD 768
#define N_HEAD 12
#define DH 64
#define N_LAYER 4
#define FF_DIM 3072
#define CHUNK 256
#define WIN 256

// ---------------- scratch (device globals; no allocation) ----------------
__device__ float g_x [S_LEN * D_MOD];
__device__ float g_q [S_LEN * D_MOD];
__device__ float g_k [S_LEN * D_MOD];
__device__ float g_v [S_LEN * D_MOD];
__device__ float g_a [S_LEN * D_MOD];
__device__ float g_o [S_LEN * D_MOD];
__device__ float g_ff[S_LEN * FF_DIM];
__device__ float g_pooled[D_MOD];
__device__ float g_h1[512];
__device__ float g_h2[256];
__device__ float g_msum[1];
// transposed weights [N][K] per layer
__device__ float g_WqT [N_LAYER * D_MOD * D_MOD];
__device__ float g_WkT [N_LAYER * D_MOD * D_MOD];
__device__ float g_WvT [N_LAYER * D_MOD * D_MOD];
__device__ float g_WoT [N_LAYER * D_MOD * D_MOD];
__device__ float g_Wf1T[N_LAYER * D_MOD * FF_DIM];
__device__ float g_Wf2T[N_LAYER * FF_DIM * D_MOD];

__device__ __forceinline__ void mma_tf32(float* d, const uint32_t* a, const uint32_t* b) {
    asm volatile(
        "mma.sync.aligned.m16n8k8.row.col.f32.tf32.tf32.f32 "
        "{%0,%1,%2,%3}, {%4,%5,%6,%7}, {%8,%9}, {%0,%1,%2,%3};\n"
        : "+f"(d[0]), "+f"(d[1]), "+f"(d[2]), "+f"(d[3])
        : "r"(a[0]), "r"(a[1]), "r"(a[2]), "r"(a[3]), "r"(b[0]), "r"(b[1]));
}

// round-to-nearest tf32 on raw f32 bits (restores round-5 numerics; the MMA
// itself truncates, so feeding RNA-rounded operands == rounding at store time)
__device__ __forceinline__ uint32_t rna_tf32_bits(uint32_t u) {
    float r;
    asm("cvt.rna.tf32.f32 %0, %1;" : "=f"(r) : "f"(__uint_as_float(u)));
    return __float_as_uint(r);
}

__device__ __forceinline__ void cp_async16(uint32_t saddr, const void* g) {
    asm volatile("cp.async.cg.shared.global [%0], [%1], 16;" :: "r"(saddr), "l"(g) : "memory");
}
#define CP_COMMIT() asm volatile("cp.async.commit_group;" ::: "memory")
#define CP_WAIT1()  asm volatile("cp.async.wait_group 1;" ::: "memory")

// ---------------- weight transpose: W[K][N] -> Wt[N][K], per-layer via blockIdx.z
__global__ void transpose_kernel(const float* __restrict__ W, float* __restrict__ Wt,
                                 int K, int N)
{
    __shared__ float t[32][33];
    size_t lo = (size_t)blockIdx.z * K * N;
    const float* Wl = W + lo;
    float* Wtl = Wt + lo;
    int k0 = blockIdx.y * 32, n0 = blockIdx.x * 32;
    int tx = threadIdx.x, ty = threadIdx.y;
#pragma unroll
    for (int i = 0; i < 32; i += 8)
        t[ty + i][tx] = Wl[(size_t)(k0 + ty + i) * N + n0 + tx];
    __syncthreads();
#pragma unroll
    for (int i = 0; i < 32; i += 8)
        Wtl[(size_t)(n0 + ty + i) * K + k0 + tx] = t[tx][ty + i];
}

// ---------------- tf32 mma.sync GEMM, cp.async 3-stage pipeline -----------
// C[M,N] = A[M,K] @ Bt[N,K]^T + bias ; epi: 0=bias, 1=bias*0.125, 2=bias+GELU
#define PAD_LD 36
#define TG_STAGES 3
#define TG_TILE (128 * PAD_LD)
#define TG_SMEM_BYTES (TG_STAGES * 2 * TG_TILE * 4)

__device__ __forceinline__ void tg_copy(const float* __restrict__ Ab,
                                        const float* __restrict__ Bb,
                                        int K, int k0,
                                        float* sA, float* sB, int tid)
{
#pragma unroll
    for (int i = 0; i < 4; i++) {
        int idx = tid + i * 256;
        int row = idx >> 3, k4 = (idx & 7) * 4;
        uint32_t da = (uint32_t)__cvta_generic_to_shared(sA + row * PAD_LD + k4);
        uint32_t db = (uint32_t)__cvta_generic_to_shared(sB + row * PAD_LD + k4);
        cp_async16(da, Ab + (size_t)row * K + k0 + k4);
        cp_async16(db, Bb + (size_t)row * K + k0 + k4);
    }
}

__global__ void __launch_bounds__(256, 2) tgemm_kernel(const float* __restrict__ A,
                                                       const float* __restrict__ Bt,
                                                       const float* __restrict__ bias,
                                                       float* __restrict__ C,
                                                       int M, int N, int K, int epi)
{
    extern __shared__ float sm[];
    float* sA = sm;                       // [3][128][36]
    float* sB = sm + TG_STAGES * TG_TILE; // [3][128][36]

    const int tid  = threadIdx.x;
    const int wid  = tid >> 5;
    const int lane = tid & 31;
    const int wm   = wid & 1;             // m offset wm*64
    const int wn   = wid >> 1;            // n offset wn*32
    const int g    = lane >> 2;
    const int cq   = lane & 3;
    const int m0 = blockIdx.y * 128;
    const int n0 = blockIdx.x * 128;
    const int NC = K >> 5;

    const float* Ab = A  + (size_t)m0 * K;
    const float* Bb = Bt + (size_t)n0 * K;

    float acc[4][4][4];
#pragma unroll
    for (int i = 0; i < 4; i++)
#pragma unroll
        for (int j = 0; j < 4; j++)
#pragma unroll
            for (int r = 0; r < 4; r++) acc[i][j][r] = 0.f;

    // prologue: stage chunks 0,1
    tg_copy(Ab, Bb, K, 0,  sA,           sB,           tid); CP_COMMIT();
    tg_copy(Ab, Bb, K, 32, sA + TG_TILE, sB + TG_TILE, tid); CP_COMMIT();

    int st = 0;
    for (int c = 0; c < NC; c++) {
        CP_WAIT1();
        __syncthreads();
        if (c + 2 < NC) {
            int ns = st + 2; if (ns >= TG_STAGES) ns -= TG_STAGES;
            tg_copy(Ab, Bb, K, (c + 2) << 5, sA + ns * TG_TILE, sB + ns * TG_TILE, tid);
            CP_COMMIT();
        }
        const float* cA = sA + st * TG_TILE;
        const float* cB = sB + st * TG_TILE;
#pragma unroll
        for (int kk = 0; kk < 4; kk++) {
            const int kb = kk * 8;
            uint32_t af[4][4], bf[4][2];
#pragma unroll
            for (int mt = 0; mt < 4; mt++) {
                int r = wm * 64 + mt * 16 + g;
                af[mt][0] = rna_tf32_bits(__float_as_uint(cA[(size_t)r       * PAD_LD + kb + cq]));
                af[mt][1] = rna_tf32_bits(__float_as_uint(cA[(size_t)(r + 8) * PAD_LD + kb + cq]));
                af[mt][2] = rna_tf32_bits(__float_as_uint(cA[(size_t)r       * PAD_LD + kb + cq + 4]));
                af[mt][3] = rna_tf32_bits(__float_as_uint(cA[(size_t)(r + 8) * PAD_LD + kb + cq + 4]));
            }
#pragma unroll
            for (int nt = 0; nt < 4; nt++) {
                int nrow = wn * 32 + nt * 8 + g;
                bf[nt][0] = rna_tf32_bits(__float_as_uint(cB[(size_t)nrow * PAD_LD + kb + cq]));
                bf[nt][1] = rna_tf32_bits(__float_as_uint(cB[(size_t)nrow * PAD_LD + kb + cq + 4]));
            }
#pragma unroll
            for (int mt = 0; mt < 4; mt++)
#pragma unroll
                for (int nt = 0; nt < 4; nt++)
                    mma_tf32(acc[mt][nt], af[mt], bf[nt]);
        }
        st++; if (st >= TG_STAGES) st = 0;
        __syncthreads();
    }

    // ---- epilogue
#pragma unroll
    for (int mt = 0; mt < 4; mt++) {
        int row = m0 + wm * 64 + mt * 16 + g;
#pragma unroll
        for (int nt = 0; nt < 4; nt++) {
            int col = n0 + wn * 32 + nt * 8 + 2 * cq;
            float bb0 = bias[col], bb1 = bias[col + 1];
            float v0 = acc[mt][nt][0] + bb0;
            float v1 = acc[mt][nt][1] + bb1;
            float v2 = acc[mt][nt][2] + bb0;
            float v3 = acc[mt][nt][3] + bb1;
            if (epi == 1) { v0 *= 0.125f; v1 *= 0.125f; v2 *= 0.125f; v3 *= 0.125f; }
            else if (epi == 2) {
                v0 = 0.5f * v0 * (1.0f + erff(v0 * 0.70710678118654752f));
                v1 = 0.5f * v1 * (1.0f + erff(v1 * 0.70710678118654752f));
                v2 = 0.5f * v2 * (1.0f + erff(v2 * 0.70710678118654752f));
                v3 = 0.5f * v3 * (1.0f + erff(v3 * 0.70710678118654752f));
            }
            *(float2*)(C + (size_t)row * N + col)       = make_float2(v0, v1);
            *(float2*)(C + (size_t)(row + 8) * N + col) = make_float2(v2, v3);
        }
    }
}

// ---------------- embedding ----------------
__global__ void embed_kernel(const int* __restrict__ ids,
                             const float* __restrict__ wemb,
                             const float* __restrict__ pemb,
                             float* __restrict__ X)
{
    int row = blockIdx.x;
    int id  = ids[row];
    const float* wp = wemb + (size_t)id * D_MOD;
    const float* pp = pemb + (size_t)row * D_MOD;
    float* xp = X + (size_t)row * D_MOD;
    for (int d = threadIdx.x; d < D_MOD; d += blockDim.x)
        xp[d] = wp[d] + pp[d];
}

// ---------------- LayerNorm (optionally with residual add), in-place on X ----
__global__ void __launch_bounds__(256) ln_kernel(float* __restrict__ X,
                                                 const float* __restrict__ Aadd,
                                                 const float* __restrict__ g,
                                                 const float* __restrict__ b)
{
    int row = blockIdx.x;
    int tid = threadIdx.x;
    __shared__ float red[256];
    float vals[3];
    float s = 0.f;
    const size_t base = (size_t)row * D_MOD;
#pragma unroll
    for (int i = 0; i < 3; i++) {
        int d = tid + i * 256;
        float v = X[base + d];
        if (Aadd) v += Aadd[base + d];
        vals[i] = v;
        s += v;
    }
    red[tid] = s; __syncthreads();
    for (int o = 128; o > 0; o >>= 1) { if (tid < o) red[tid] += red[tid + o]; __syncthreads(); }
    float mean = red[0] * (1.0f / D_MOD);
    __syncthreads();
    float ss = 0.f;
#pragma unroll
    for (int i = 0; i < 3; i++) { float dv = vals[i] - mean; ss += dv * dv; }
    red[tid] = ss; __syncthreads();
    for (int o = 128; o > 0; o >>= 1) { if (tid < o) red[tid] += red[tid + o]; __syncthreads(); }
    float rstd = rsqrtf(red[0] * (1.0f / D_MOD) + 1e-5f);
#pragma unroll
    for (int i = 0; i < 3; i++) {
        int d = tid + i * 256;
        X[base + d] = (vals[i] - mean) * rstd * g[d] + b[d];
    }
}

// ---------------- band attention: split-D flash, 2 threads per query --------
// Shuffle uses the 2-lane pair mask: both lanes of a pair share the same query
// (identical loop bounds) so they are always converged.
#define QB 128
__global__ void __launch_bounds__(256) attn_kernel(const float* __restrict__ Q,
                                                   const float* __restrict__ K,
                                                   const float* __restrict__ V,
                                                   const int* __restrict__ mask,
                                                   float* __restrict__ O)
{
    const int cb  = blockIdx.x;   // half-chunk 0..31
    const int h   = blockIdx.y;   // head 0..11
    const int tid = threadIdx.x;
    const int qi   = tid >> 1;    // query in block 0..127
    const int half = tid & 1;     // D half
    const int lane = tid & 31;
    const unsigned pair_mask = 0x3u << (lane & 30);
    const int sq = cb * QB + qi;

    __shared__ float ks[64][64];
    __shared__ float vs[64][64];
    __shared__ float mt[64];

    float qreg[32];
    const float* qp = Q + (size_t)sq * D_MOD + h * DH + half * 32;
#pragma unroll
    for (int i = 0; i < 8; i++) {
        float4 qv = *(const float4*)(qp + i * 4);
        qreg[i * 4 + 0] = qv.x; qreg[i * 4 + 1] = qv.y;
        qreg[i * 4 + 2] = qv.z; qreg[i * 4 + 3] = qv.w;
    }

    float m = -1e30f, l = 0.f;
    float acc[32];
#pragma unroll
    for (int d = 0; d < 32; d++) acc[d] = 0.f;

    int lo = sq - WIN; if (lo < 0) lo = 0;
    int hi = sq + WIN; if (hi > S_LEN - 1) hi = S_LEN - 1;
    const int base = cb * QB - WIN;               // lowest key for block
    int blo = base;           if (blo < 0) blo = 0;
    int bhi = base + QB - 1 + 2 * WIN; if (bhi > S_LEN - 1) bhi = S_LEN - 1;

    for (int t = 0; t < (QB + 2 * WIN) / 64; t++) {   // 10 tiles
        int tstart = base + t * 64;
        if (tstart + 63 < blo || tstart > bhi) continue;
        __syncthreads();
#pragma unroll
        for (int i = 0; i < 4; i++) {
            int e  = tid + i * 256;              // 0..1023
            int jj = e >> 4, d4 = (e & 15) * 4;
            int g2 = tstart + jj;
            float4 kv = make_float4(0.f, 0.f, 0.f, 0.f);
            float4 vv = kv;
            if (g2 >= 0 && g2 < S_LEN) {
                size_t off = (size_t)g2 * D_MOD + h * DH + d4;
                kv = *(const float4*)(K + off);
                vv = *(const float4*)(V + off);
            }
            *(float4*)&ks[jj][d4] = kv;
            *(float4*)&vs[jj][d4] = vv;
        }
        if (tid < 64) {
            int g2 = tstart + tid;
            mt[tid] = (g2 >= 0 && g2 < S_LEN && mask[g2] != 0) ? 1.f : 0.f;
        }
        __syncthreads();
        int j0 = lo - tstart; if (j0 < 0) j0 = 0;
        int j1 = hi - tstart; if (j1 > 63) j1 = 63;
        const int dc = half * 32;
        for (int jj = j0; jj <= j1; jj++) {
            if (mt[jj] == 0.f) continue;
            float part = 0.f;
#pragma unroll
            for (int d = 0; d < 32; d++) part += qreg[d] * ks[jj][dc + d];
            float other = __shfl_xor_sync(pair_mask, part, 1);
            float s = part + other;   // FP add commutative -> identical in both lanes
            if (s <= m) {
                float p = __expf(s - m);
                l += p;
#pragma unroll
                for (int d = 0; d < 32; d++) acc[d] += p * vs[jj][dc + d];
            } else {
                float sc = __expf(m - s);
                l = l * sc + 1.0f;
#pragma unroll
                for (int d = 0; d < 32; d++) acc[d] = acc[d] * sc + vs[jj][dc + d];
                m = s;
            }
        }
    }
    float inv = 1.0f / l;
    float* op = O + (size_t)sq * D_MOD + h * DH + half * 32;
#pragma unroll
    for (int i = 0; i < 8; i++) {
        float4 ov = make_float4(acc[i*4] * inv, acc[i*4+1] * inv,
                                acc[i*4+2] * inv, acc[i*4+3] * inv);
        *(float4*)(op + i * 4) = ov;
    }
}

// ---------------- pooling + head ----------------
__global__ void zero_pooled_kernel(float* __restrict__ pooled)
{
    for (int d = threadIdx.x; d < D_MOD; d += blockDim.x) pooled[d] = 0.f;
}

__global__ void msum_kernel(const int* __restrict__ mask, float* __restrict__ out)
{
    __shared__ float red[256];
    int tid = threadIdx.x;
    float s = 0.f;
    for (int i = tid; i < S_LEN; i += 256) s += (float)mask[i];
    red[tid] = s; __syncthreads();
    for (int o = 128; o > 0; o >>= 1) { if (tid < o) red[tid] += red[tid + o]; __syncthreads(); }
    if (tid == 0) out[0] = fmaxf(red[0], 1e-9f);
}

__global__ void __launch_bounds__(256) pool_kernel(const float* __restrict__ X,
                                                   const int* __restrict__ mask,
                                                   float* __restrict__ pooled)
{
    int s0 = blockIdx.x * 256;
    int tid = threadIdx.x;
    float a0 = 0.f, a1 = 0.f, a2 = 0.f;
    for (int r = 0; r < 256; r++) {
        float mf = (float)mask[s0 + r];
        const float* xp = X + (size_t)(s0 + r) * D_MOD;
        a0 += xp[tid]       * mf;
        a1 += xp[tid + 256] * mf;
        a2 += xp[tid + 512] * mf;
    }
    atomicAdd(&pooled[tid],       a0);
    atomicAdd(&pooled[tid + 256], a1);
    atomicAdd(&pooled[tid + 512], a2);
}

__global__ void head1_kernel(const float* __restrict__ pooled,
                             const float* __restrict__ W1, const float* __restrict__ b1,
                             const float* __restrict__ msum, float* __restrict__ h1)
{
    int i = threadIdx.x;   // 512 threads
    float inv = 1.0f / msum[0];
    float dot = 0.f;
    for (int d = 0; d < D_MOD; d++) dot += pooled[d] * W1[(size_t)d * 512 + i];
    h1[i] = fmaxf(dot * inv + b1[i], 0.f);
}

__global__ void head2_kernel(const float* __restrict__ h1,
                             const float* __restrict__ W2, const float* __restrict__ b2,
                             float* __restrict__ h2)
{
    int i = threadIdx.x;   // 256 threads
    if (i < 250) {
        float dot = 0.f;
        for (int d = 0; d < 512; d++) dot += h1[d] * W2[(size_t)d * 250 + i];
        h2[i] = fmaxf(dot + b2[i], 0.f);
    } else if (i < 256) {
        h2[i] = 0.f;
    }
}

__global__ void head3_kernel(const float* __restrict__ h2,
                             const float* __restrict__ W3, const float* __restrict__ b3,
                             float* __restrict__ out, int out_size)
{
    __shared__ float red[256];
    __shared__ float pred;
    int tid = threadIdx.x;
    float v = (tid < 250) ? h2[tid] * W3[tid] : 0.f;
    red[tid] = v; __syncthreads();
    for (int o = 128; o > 0; o >>= 1) { if (tid < o) red[tid] += red[tid + o]; __syncthreads(); }
    if (tid == 0) pred = red[0] + b3[0];
    __syncthreads();
    for (int i = tid; i < out_size; i += 256) out[i] = pred;
}

// ---------------- launch ----------------
extern "C" void kernel_launch(void* const* d_in, const int* in_sizes, int n_in,
                              void* d_out, int out_size)
{
    const int*   ids    = (const int*)  d_in[0];
    const int*   mask   = (const int*)  d_in[1];
    const float* wemb   = (const float*)d_in[2];
    const float* pemb   = (const float*)d_in[3];
    const float* emb_g  = (const float*)d_in[4];
    const float* emb_b  = (const float*)d_in[5];
    const float* Wq     = (const float*)d_in[6];
    const float* Wk     = (const float*)d_in[7];
    const float* Wv     = (const float*)d_in[8];
    const float* Wo     = (const float*)d_in[9];
    const float* bq     = (const float*)d_in[10];
    const float* bk     = (const float*)d_in[11];
    const float* bv     = (const float*)d_in[12];
    const float* bo     = (const float*)d_in[13];
    const float* ln1_g  = (const float*)d_in[14];
    const float* ln1_b  = (const float*)d_in[15];
    const float* Wff1   = (const float*)d_in[16];
    const float* bff1   = (const float*)d_in[17];
    const float* Wff2   = (const float*)d_in[18];
    const float* bff2   = (const float*)d_in[19];
    const float* ln2_g  = (const float*)d_in[20];
    const float* ln2_b  = (const float*)d_in[21];
    const float* W1     = (const float*)d_in[22];
    const float* b1     = (const float*)d_in[23];
    const float* W2     = (const float*)d_in[24];
    const float* b2     = (const float*)d_in[25];
    const float* W3     = (const float*)d_in[26];
    const float* b3     = (const float*)d_in[27];
    float* out = (float*)d_out;

    float *x, *q, *k, *v, *a, *o, *ff, *pooled, *h1, *h2, *msum;
    float *WqT, *WkT, *WvT, *WoT, *Wf1T, *Wf2T;
    cudaGetSymbolAddress((void**)&x,      g_x);
    cudaGetSymbolAddress((void**)&q,      g_q);
    cudaGetSymbolAddress((void**)&k,      g_k);
    cudaGetSymbolAddress((void**)&v,      g_v);
    cudaGetSymbolAddress((void**)&a,      g_a);
    cudaGetSymbolAddress((void**)&o,      g_o);
    cudaGetSymbolAddress((void**)&ff,     g_ff);
    cudaGetSymbolAddress((void**)&pooled, g_pooled);
    cudaGetSymbolAddress((void**)&h1,     g_h1);
    cudaGetSymbolAddress((void**)&h2,     g_h2);
    cudaGetSymbolAddress((void**)&msum,   g_msum);
    cudaGetSymbolAddress((void**)&WqT,    g_WqT);
    cudaGetSymbolAddress((void**)&WkT,    g_WkT);
    cudaGetSymbolAddress((void**)&WvT,    g_WvT);
    cudaGetSymbolAddress((void**)&WoT,    g_WoT);
    cudaGetSymbolAddress((void**)&Wf1T,   g_Wf1T);
    cudaGetSymbolAddress((void**)&Wf2T,   g_Wf2T);

    cudaFuncSetAttribute(tgemm_kernel, cudaFuncAttributeMaxDynamicSharedMemorySize, TG_SMEM_BYTES);

    // transpose weights: W[K][N] -> Wt[N][K]
    {
        dim3 tb(32, 8);
        transpose_kernel<<<dim3(D_MOD/32, D_MOD/32, N_LAYER), tb>>>(Wq,   WqT,  D_MOD, D_MOD);
        transpose_kernel<<<dim3(D_MOD/32, D_MOD/32, N_LAYER), tb>>>(Wk,   WkT,  D_MOD, D_MOD);
        transpose_kernel<<<dim3(D_MOD/32, D_MOD/32, N_LAYER), tb>>>(Wv,   WvT,  D_MOD, D_MOD);
        transpose_kernel<<<dim3(D_MOD/32, D_MOD/32, N_LAYER), tb>>>(Wo,   WoT,  D_MOD, D_MOD);
        transpose_kernel<<<dim3(FF_DIM/32, D_MOD/32, N_LAYER), tb>>>(Wff1, Wf1T, D_MOD, FF_DIM);
        transpose_kernel<<<dim3(D_MOD/32, FF_DIM/32, N_LAYER), tb>>>(Wff2, Wf2T, FF_DIM, D_MOD);
    }

    dim3 tg768 (D_MOD / 128, S_LEN / 128);   // (6, 32)
    dim3 tg3072(FF_DIM / 128, S_LEN / 128);  // (24, 32)

    embed_kernel<<<S_LEN, 256>>>(ids, wemb, pemb, x);
    ln_kernel<<<S_LEN, 256>>>(x, nullptr, emb_g, emb_b);

    for (int l = 0; l < N_LAYER; l++) {
        const float* WqT_l  = WqT  + (size_t)l * D_MOD * D_MOD;
        const float* WkT_l  = WkT  + (size_t)l * D_MOD * D_MOD;
        const float* WvT_l  = WvT  + (size_t)l * D_MOD * D_MOD;
        const float* WoT_l  = WoT  + (size_t)l * D_MOD * D_MOD;
        const float* Wf1T_l = Wf1T + (size_t)l * D_MOD * FF_DIM;
        const float* Wf2T_l = Wf2T + (size_t)l * FF_DIM * D_MOD;

        tgemm_kernel<<<tg768, 256, TG_SMEM_BYTES>>>(x, WqT_l, bq + l * D_MOD, q, S_LEN, D_MOD, D_MOD, 1);
        tgemm_kernel<<<tg768, 256, TG_SMEM_BYTES>>>(x, WkT_l, bk + l * D_MOD, k, S_LEN, D_MOD, D_MOD, 0);
        tgemm_kernel<<<tg768, 256, TG_SMEM_BYTES>>>(x, WvT_l, bv + l * D_MOD, v, S_LEN, D_MOD, D_MOD, 0);

        attn_kernel<<<dim3(S_LEN / QB, N_HEAD), 256>>>(q, k, v, mask, a);

        tgemm_kernel<<<tg768, 256, TG_SMEM_BYTES>>>(a, WoT_l, bo + l * D_MOD, o, S_LEN, D_MOD, D_MOD, 0);
        ln_kernel<<<S_LEN, 256>>>(x, o, ln1_g + l * D_MOD, ln1_b + l * D_MOD);

        tgemm_kernel<<<tg3072, 256, TG_SMEM_BYTES>>>(x, Wf1T_l, bff1 + l * FF_DIM, ff, S_LEN, FF_DIM, D_MOD, 2);
        tgemm_kernel<<<tg768,  256, TG_SMEM_BYTES>>>(ff, Wf2T_l, bff2 + l * D_MOD, o, S_LEN, D_MOD, FF_DIM, 0);
        ln_kernel<<<S_LEN, 256>>>(x, o, ln2_g + l * D_MOD, ln2_b + l * D_MOD);
    }

    zero_pooled_kernel<<<1, 256>>>(pooled);
    msum_kernel<<<1, 256>>>(mask, msum);
    pool_kernel<<<S_LEN / 256, 256>>>(x, mask, pooled);
    head1_kernel<<<1, 512>>>(pooled, W1, b1, msum, h1);
    head2_kernel<<<1, 256>>>(h1, W2, b2, h2);
    head3_kernel<<<1, 256>>>(h2, W3, b3, out, out_size);
}

// round 10
// speedup vs baseline: 2.0355x; 1.0494x over previous
#include <cuda_runtime.h>
#include <cuda_bf16.h>
#include <math.h>
#include <stdint.h>

#define S_LEN 4096
#define D_MOD 768
#define N_HEAD 12
#define DH 64
#define N_LAYER 4
#define FF_DIM 3072
#define CHUNK 256
#define WIN 256

// ---------------- scratch (device globals; no allocation) ----------------
__device__ float g_x [S_LEN * D_MOD];
__device__ float g_xr[S_LEN * D_MOD];   // tf32-rounded copy of x (GEMM A operand)
__device__ float g_q [S_LEN * D_MOD];
__device__ float g_k [S_LEN * D_MOD];
__device__ float g_v [S_LEN * D_MOD];
__device__ float g_a [S_LEN * D_MOD];   // attention out, pre-rounded
__device__ float g_o [S_LEN * D_MOD];
__device__ float g_ff[S_LEN * FF_DIM];  // FF1 out, pre-rounded
__device__ float g_pooled[D_MOD];
__device__ float g_h1[512];
__device__ float g_h2[256];
__device__ float g_msum[1];
// transposed + tf32-rounded weights [N][K] per layer
__device__ float g_WqT [N_LAYER * D_MOD * D_MOD];
__device__ float g_WkT [N_LAYER * D_MOD * D_MOD];
__device__ float g_WvT [N_LAYER * D_MOD * D_MOD];
__device__ float g_WoT [N_LAYER * D_MOD * D_MOD];
__device__ float g_Wf1T[N_LAYER * D_MOD * FF_DIM];
__device__ float g_Wf2T[N_LAYER * FF_DIM * D_MOD];

__device__ __forceinline__ float rna_tf32(float x) {
    float r; asm("cvt.rna.tf32.f32 %0, %1;" : "=f"(r) : "f"(x)); return r;
}

__device__ __forceinline__ void mma_tf32(float* d, const uint32_t* a, const uint32_t* b) {
    asm volatile(
        "mma.sync.aligned.m16n8k8.row.col.f32.tf32.tf32.f32 "
        "{%0,%1,%2,%3}, {%4,%5,%6,%7}, {%8,%9}, {%0,%1,%2,%3};\n"
        : "+f"(d[0]), "+f"(d[1]), "+f"(d[2]), "+f"(d[3])
        : "r"(a[0]), "r"(a[1]), "r"(a[2]), "r"(a[3]), "r"(b[0]), "r"(b[1]));
}

__device__ __forceinline__ void cp_async16(uint32_t saddr, const void* g) {
    asm volatile("cp.async.cg.shared.global [%0], [%1], 16;" :: "r"(saddr), "l"(g) : "memory");
}
#define CP_COMMIT() asm volatile("cp.async.commit_group;" ::: "memory")
#define CP_WAIT1()  asm volatile("cp.async.wait_group 1;" ::: "memory")
#define CP_WAIT0()  asm volatile("cp.async.wait_group 0;" ::: "memory")

// ------- weight transpose + tf32 RNA rounding: W[K][N] -> Wt[N][K] ---------
__global__ void transpose_kernel(const float* __restrict__ W, float* __restrict__ Wt,
                                 int K, int N)
{
    __shared__ float t[32][33];
    size_t lo = (size_t)blockIdx.z * K * N;
    const float* Wl = W + lo;
    float* Wtl = Wt + lo;
    int k0 = blockIdx.y * 32, n0 = blockIdx.x * 32;
    int tx = threadIdx.x, ty = threadIdx.y;
#pragma unroll
    for (int i = 0; i < 32; i += 8)
        t[ty + i][tx] = Wl[(size_t)(k0 + ty + i) * N + n0 + tx];
    __syncthreads();
#pragma unroll
    for (int i = 0; i < 32; i += 8)
        Wtl[(size_t)(n0 + ty + i) * K + k0 + tx] = rna_tf32(t[tx][ty + i]);
}

// ---------------- tf32 mma.sync GEMM, cp.async 3-stage pipeline -----------
// All operands PRE-ROUNDED to tf32 (zero cvts in hot loop).
// epi: 0=bias, 1=bias*0.125, 2=bias+GELU+round-out (FF1 -> FF2's A operand)
#define PAD_LD 36
#define TG_STAGES 3
#define TG_TILE (128 * PAD_LD)
#define TG_SMEM_BYTES (TG_STAGES * 2 * TG_TILE * 4)

__device__ __forceinline__ void tg_copy(const float* __restrict__ Ab,
                                        const float* __restrict__ Bb,
                                        int K, int k0,
                                        float* sA, float* sB, int tid)
{
#pragma unroll
    for (int i = 0; i < 4; i++) {
        int idx = tid + i * 256;
        int row = idx >> 3, k4 = (idx & 7) * 4;
        uint32_t da = (uint32_t)__cvta_generic_to_shared(sA + row * PAD_LD + k4);
        uint32_t db = (uint32_t)__cvta_generic_to_shared(sB + row * PAD_LD + k4);
        cp_async16(da, Ab + (size_t)row * K + k0 + k4);
        cp_async16(db, Bb + (size_t)row * K + k0 + k4);
    }
}

__global__ void __launch_bounds__(256, 2) tgemm_kernel(const float* __restrict__ A,
                                                       const float* __restrict__ Bt,
                                                       const float* __restrict__ bias,
                                                       float* __restrict__ C,
                                                       int M, int N, int K, int epi)
{
    extern __shared__ float sm[];
    float* sA = sm;                       // [3][128][36]
    float* sB = sm + TG_STAGES * TG_TILE; // [3][128][36]

    const int tid  = threadIdx.x;
    const int wid  = tid >> 5;
    const int lane = tid & 31;
    const int wm   = wid & 1;             // m offset wm*64
    const int wn   = wid >> 1;            // n offset wn*32
    const int g    = lane >> 2;
    const int cq   = lane & 3;
    const int m0 = blockIdx.y * 128;
    const int n0 = blockIdx.x * 128;
    const int NC = K >> 5;

    const float* Ab = A  + (size_t)m0 * K;
    const float* Bb = Bt + (size_t)n0 * K;

    float acc[4][4][4];
#pragma unroll
    for (int i = 0; i < 4; i++)
#pragma unroll
        for (int j = 0; j < 4; j++)
#pragma unroll
            for (int r = 0; r < 4; r++) acc[i][j][r] = 0.f;

    // prologue: stage chunks 0,1
    tg_copy(Ab, Bb, K, 0,  sA,           sB,           tid); CP_COMMIT();
    tg_copy(Ab, Bb, K, 32, sA + TG_TILE, sB + TG_TILE, tid); CP_COMMIT();

    int st = 0;
    for (int c = 0; c < NC; c++) {
        if (c + 1 < NC) { CP_WAIT1(); } else { CP_WAIT0(); }
        __syncthreads();   // single barrier: also protects stage (st+2) overwrite
        if (c + 2 < NC) {
            int ns = st + 2; if (ns >= TG_STAGES) ns -= TG_STAGES;
            tg_copy(Ab, Bb, K, (c + 2) << 5, sA + ns * TG_TILE, sB + ns * TG_TILE, tid);
            CP_COMMIT();
        }
        const float* cA = sA + st * TG_TILE;
        const float* cB = sB + st * TG_TILE;
#pragma unroll
        for (int kk = 0; kk < 4; kk++) {
            const int kb = kk * 8;
            uint32_t af[4][4], bf[4][2];
#pragma unroll
            for (int mt = 0; mt < 4; mt++) {
                int r = wm * 64 + mt * 16 + g;
                af[mt][0] = __float_as_uint(cA[(size_t)r       * PAD_LD + kb + cq]);
                af[mt][1] = __float_as_uint(cA[(size_t)(r + 8) * PAD_LD + kb + cq]);
                af[mt][2] = __float_as_uint(cA[(size_t)r       * PAD_LD + kb + cq + 4]);
                af[mt][3] = __float_as_uint(cA[(size_t)(r + 8) * PAD_LD + kb + cq + 4]);
            }
#pragma unroll
            for (int nt = 0; nt < 4; nt++) {
                int nrow = wn * 32 + nt * 8 + g;
                bf[nt][0] = __float_as_uint(cB[(size_t)nrow * PAD_LD + kb + cq]);
                bf[nt][1] = __float_as_uint(cB[(size_t)nrow * PAD_LD + kb + cq + 4]);
            }
#pragma unroll
            for (int mt = 0; mt < 4; mt++)
#pragma unroll
                for (int nt = 0; nt < 4; nt++)
                    mma_tf32(acc[mt][nt], af[mt], bf[nt]);
        }
        st++; if (st >= TG_STAGES) st = 0;
    }

    // ---- epilogue
#pragma unroll
    for (int mt = 0; mt < 4; mt++) {
        int row = m0 + wm * 64 + mt * 16 + g;
#pragma unroll
        for (int nt = 0; nt < 4; nt++) {
            int col = n0 + wn * 32 + nt * 8 + 2 * cq;
            float bb0 = bias[col], bb1 = bias[col + 1];
            float v0 = acc[mt][nt][0] + bb0;
            float v1 = acc[mt][nt][1] + bb1;
            float v2 = acc[mt][nt][2] + bb0;
            float v3 = acc[mt][nt][3] + bb1;
            if (epi == 1) { v0 *= 0.125f; v1 *= 0.125f; v2 *= 0.125f; v3 *= 0.125f; }
            else if (epi == 2) {
                v0 = rna_tf32(0.5f * v0 * (1.0f + erff(v0 * 0.70710678118654752f)));
                v1 = rna_tf32(0.5f * v1 * (1.0f + erff(v1 * 0.70710678118654752f)));
                v2 = rna_tf32(0.5f * v2 * (1.0f + erff(v2 * 0.70710678118654752f)));
                v3 = rna_tf32(0.5f * v3 * (1.0f + erff(v3 * 0.70710678118654752f)));
            }
            *(float2*)(C + (size_t)row * N + col)       = make_float2(v0, v1);
            *(float2*)(C + (size_t)(row + 8) * N + col) = make_float2(v2, v3);
        }
    }
}

// ---------------- embedding ----------------
__global__ void embed_kernel(const int* __restrict__ ids,
                             const float* __restrict__ wemb,
                             const float* __restrict__ pemb,
                             float* __restrict__ X)
{
    int row = blockIdx.x;
    int id  = ids[row];
    const float* wp = wemb + (size_t)id * D_MOD;
    const float* pp = pemb + (size_t)row * D_MOD;
    float* xp = X + (size_t)row * D_MOD;
    for (int d = threadIdx.x; d < D_MOD; d += blockDim.x)
        xp[d] = wp[d] + pp[d];
}

// -------- LayerNorm (optional residual add), in-place on X; optional XR ----
// XR (if non-null) receives the tf32-RNA-rounded copy (GEMM A operand).
__global__ void __launch_bounds__(256) ln_kernel(float* __restrict__ X,
                                                 const float* __restrict__ Aadd,
                                                 const float* __restrict__ g,
                                                 const float* __restrict__ b,
                                                 float* __restrict__ XR)
{
    int row = blockIdx.x;
    int tid = threadIdx.x;
    int lane = tid & 31, wid = tid >> 5;
    __shared__ float red[8];
    float vals[3];
    float s = 0.f;
    const size_t base = (size_t)row * D_MOD;
#pragma unroll
    for (int i = 0; i < 3; i++) {
        int d = tid + i * 256;
        float v = X[base + d];
        if (Aadd) v += Aadd[base + d];
        vals[i] = v;
        s += v;
    }
#pragma unroll
    for (int o = 16; o > 0; o >>= 1) s += __shfl_xor_sync(0xFFFFFFFFu, s, o);
    if (lane == 0) red[wid] = s;
    __syncthreads();
    float tot = red[0] + red[1] + red[2] + red[3] + red[4] + red[5] + red[6] + red[7];
    float mean = tot * (1.0f / D_MOD);
    float ss = 0.f;
#pragma unroll
    for (int i = 0; i < 3; i++) { float dv = vals[i] - mean; ss += dv * dv; }
#pragma unroll
    for (int o = 16; o > 0; o >>= 1) ss += __shfl_xor_sync(0xFFFFFFFFu, ss, o);
    __syncthreads();
    if (lane == 0) red[wid] = ss;
    __syncthreads();
    float tot2 = red[0] + red[1] + red[2] + red[3] + red[4] + red[5] + red[6] + red[7];
    float rstd = rsqrtf(tot2 * (1.0f / D_MOD) + 1e-5f);
#pragma unroll
    for (int i = 0; i < 3; i++) {
        int d = tid + i * 256;
        float outv = (vals[i] - mean) * rstd * g[d] + b[d];
        X[base + d] = outv;
        if (XR) XR[base + d] = rna_tf32(outv);
    }
}

// ---------------- band attention: split-D flash, 2 threads per query --------
// Output is tf32-RNA-rounded (it feeds only the O-projection GEMM's A operand).
#define QB 128
__global__ void __launch_bounds__(256) attn_kernel(const float* __restrict__ Q,
                                                   const float* __restrict__ K,
                                                   const float* __restrict__ V,
                                                   const int* __restrict__ mask,
                                                   float* __restrict__ O)
{
    const int cb  = blockIdx.x;   // half-chunk 0..31
    const int h   = blockIdx.y;   // head 0..11
    const int tid = threadIdx.x;
    const int qi   = tid >> 1;    // query in block 0..127
    const int half = tid & 1;     // D half
    const int lane = tid & 31;
    const unsigned pair_mask = 0x3u << (lane & 30);
    const int sq = cb * QB + qi;

    __shared__ float ks[64][64];
    __shared__ float vs[64][64];
    __shared__ float mt[64];

    float qreg[32];
    const float* qp = Q + (size_t)sq * D_MOD + h * DH + half * 32;
#pragma unroll
    for (int i = 0; i < 8; i++) {
        float4 qv = *(const float4*)(qp + i * 4);
        qreg[i * 4 + 0] = qv.x; qreg[i * 4 + 1] = qv.y;
        qreg[i * 4 + 2] = qv.z; qreg[i * 4 + 3] = qv.w;
    }

    float m = -1e30f, l = 0.f;
    float acc[32];
#pragma unroll
    for (int d = 0; d < 32; d++) acc[d] = 0.f;

    int lo = sq - WIN; if (lo < 0) lo = 0;
    int hi = sq + WIN; if (hi > S_LEN - 1) hi = S_LEN - 1;
    const int base = cb * QB - WIN;
    int blo = base;           if (blo < 0) blo = 0;
    int bhi = base + QB - 1 + 2 * WIN; if (bhi > S_LEN - 1) bhi = S_LEN - 1;

    for (int t = 0; t < (QB + 2 * WIN) / 64; t++) {   // 10 tiles
        int tstart = base + t * 64;
        if (tstart + 63 < blo || tstart > bhi) continue;
        __syncthreads();
#pragma unroll
        for (int i = 0; i < 4; i++) {
            int e  = tid + i * 256;
            int jj = e >> 4, d4 = (e & 15) * 4;
            int g2 = tstart + jj;
            float4 kv = make_float4(0.f, 0.f, 0.f, 0.f);
            float4 vv = kv;
            if (g2 >= 0 && g2 < S_LEN) {
                size_t off = (size_t)g2 * D_MOD + h * DH + d4;
                kv = *(const float4*)(K + off);
                vv = *(const float4*)(V + off);
            }
            *(float4*)&ks[jj][d4] = kv;
            *(float4*)&vs[jj][d4] = vv;
        }
        if (tid < 64) {
            int g2 = tstart + tid;
            mt[tid] = (g2 >= 0 && g2 < S_LEN && mask[g2] != 0) ? 1.f : 0.f;
        }
        __syncthreads();
        int j0 = lo - tstart; if (j0 < 0) j0 = 0;
        int j1 = hi - tstart; if (j1 > 63) j1 = 63;
        const int dc = half * 32;
        for (int jj = j0; jj <= j1; jj++) {
            if (mt[jj] == 0.f) continue;
            float part = 0.f;
#pragma unroll
            for (int d = 0; d < 32; d++) part += qreg[d] * ks[jj][dc + d];
            float other = __shfl_xor_sync(pair_mask, part, 1);
            float s = part + other;
            if (s <= m) {
                float p = __expf(s - m);
                l += p;
#pragma unroll
                for (int d = 0; d < 32; d++) acc[d] += p * vs[jj][dc + d];
            } else {
                float sc = __expf(m - s);
                l = l * sc + 1.0f;
#pragma unroll
                for (int d = 0; d < 32; d++) acc[d] = acc[d] * sc + vs[jj][dc + d];
                m = s;
            }
        }
    }
    float inv = 1.0f / l;
    float* op = O + (size_t)sq * D_MOD + h * DH + half * 32;
#pragma unroll
    for (int i = 0; i < 8; i++) {
        float4 ov = make_float4(rna_tf32(acc[i*4] * inv), rna_tf32(acc[i*4+1] * inv),
                                rna_tf32(acc[i*4+2] * inv), rna_tf32(acc[i*4+3] * inv));
        *(float4*)(op + i * 4) = ov;
    }
}

// ---------------- pooling + head ----------------
__global__ void zero_pooled_kernel(float* __restrict__ pooled)
{
    for (int d = threadIdx.x; d < D_MOD; d += blockDim.x) pooled[d] = 0.f;
}

__global__ void msum_kernel(const int* __restrict__ mask, float* __restrict__ out)
{
    __shared__ float red[256];
    int tid = threadIdx.x;
    float s = 0.f;
    for (int i = tid; i < S_LEN; i += 256) s += (float)mask[i];
    red[tid] = s; __syncthreads();
    for (int o = 128; o > 0; o >>= 1) { if (tid < o) red[tid] += red[tid + o]; __syncthreads(); }
    if (tid == 0) out[0] = fmaxf(red[0], 1e-9f);
}

__global__ void __launch_bounds__(256) pool_kernel(const float* __restrict__ X,
                                                   const int* __restrict__ mask,
                                                   float* __restrict__ pooled)
{
    int s0 = blockIdx.x * 256;
    int tid = threadIdx.x;
    float a0 = 0.f, a1 = 0.f, a2 = 0.f;
    for (int r = 0; r < 256; r++) {
        float mf = (float)mask[s0 + r];
        const float* xp = X + (size_t)(s0 + r) * D_MOD;
        a0 += xp[tid]       * mf;
        a1 += xp[tid + 256] * mf;
        a2 += xp[tid + 512] * mf;
    }
    atomicAdd(&pooled[tid],       a0);
    atomicAdd(&pooled[tid + 256], a1);
    atomicAdd(&pooled[tid + 512], a2);
}

__global__ void head1_kernel(const float* __restrict__ pooled,
                             const float* __restrict__ W1, const float* __restrict__ b1,
                             const float* __restrict__ msum, float* __restrict__ h1)
{
    int i = threadIdx.x;   // 512 threads
    float inv = 1.0f / msum[0];
    float dot = 0.f;
    for (int d = 0; d < D_MOD; d++) dot += pooled[d] * W1[(size_t)d * 512 + i];
    h1[i] = fmaxf(dot * inv + b1[i], 0.f);
}

__global__ void head2_kernel(const float* __restrict__ h1,
                             const float* __restrict__ W2, const float* __restrict__ b2,
                             float* __restrict__ h2)
{
    int i = threadIdx.x;   // 256 threads
    if (i < 250) {
        float dot = 0.f;
        for (int d = 0; d < 512; d++) dot += h1[d] * W2[(size_t)d * 250 + i];
        h2[i] = fmaxf(dot + b2[i], 0.f);
    } else if (i < 256) {
        h2[i] = 0.f;
    }
}

__global__ void head3_kernel(const float* __restrict__ h2,
                             const float* __restrict__ W3, const float* __restrict__ b3,
                             float* __restrict__ out, int out_size)
{
    __shared__ float red[256];
    __shared__ float pred;
    int tid = threadIdx.x;
    float v = (tid < 250) ? h2[tid] * W3[tid] : 0.f;
    red[tid] = v; __syncthreads();
    for (int o = 128; o > 0; o >>= 1) { if (tid < o) red[tid] += red[tid + o]; __syncthreads(); }
    if (tid == 0) pred = red[0] + b3[0];
    __syncthreads();
    for (int i = tid; i < out_size; i += 256) out[i] = pred;
}

// ---------------- launch ----------------
extern "C" void kernel_launch(void* const* d_in, const int* in_sizes, int n_in,
                              void* d_out, int out_size)
{
    const int*   ids    = (const int*)  d_in[0];
    const int*   mask   = (const int*)  d_in[1];
    const float* wemb   = (const float*)d_in[2];
    const float* pemb   = (const float*)d_in[3];
    const float* emb_g  = (const float*)d_in[4];
    const float* emb_b  = (const float*)d_in[5];
    const float* Wq     = (const float*)d_in[6];
    const float* Wk     = (const float*)d_in[7];
    const float* Wv     = (const float*)d_in[8];
    const float* Wo     = (const float*)d_in[9];
    const float* bq     = (const float*)d_in[10];
    const float* bk     = (const float*)d_in[11];
    const float* bv     = (const float*)d_in[12];
    const float* bo     = (const float*)d_in[13];
    const float* ln1_g  = (const float*)d_in[14];
    const float* ln1_b  = (const float*)d_in[15];
    const float* Wff1   = (const float*)d_in[16];
    const float* bff1   = (const float*)d_in[17];
    const float* Wff2   = (const float*)d_in[18];
    const float* bff2   = (const float*)d_in[19];
    const float* ln2_g  = (const float*)d_in[20];
    const float* ln2_b  = (const float*)d_in[21];
    const float* W1     = (const float*)d_in[22];
    const float* b1     = (const float*)d_in[23];
    const float* W2     = (const float*)d_in[24];
    const float* b2     = (const float*)d_in[25];
    const float* W3     = (const float*)d_in[26];
    const float* b3     = (const float*)d_in[27];
    float* out = (float*)d_out;

    float *x, *xr, *q, *k, *v, *a, *o, *ff, *pooled, *h1, *h2, *msum;
    float *WqT, *WkT, *WvT, *WoT, *Wf1T, *Wf2T;
    cudaGetSymbolAddress((void**)&x,      g_x);
    cudaGetSymbolAddress((void**)&xr,     g_xr);
    cudaGetSymbolAddress((void**)&q,      g_q);
    cudaGetSymbolAddress((void**)&k,      g_k);
    cudaGetSymbolAddress((void**)&v,      g_v);
    cudaGetSymbolAddress((void**)&a,      g_a);
    cudaGetSymbolAddress((void**)&o,      g_o);
    cudaGetSymbolAddress((void**)&ff,     g_ff);
    cudaGetSymbolAddress((void**)&pooled, g_pooled);
    cudaGetSymbolAddress((void**)&h1,     g_h1);
    cudaGetSymbolAddress((void**)&h2,     g_h2);
    cudaGetSymbolAddress((void**)&msum,   g_msum);
    cudaGetSymbolAddress((void**)&WqT,    g_WqT);
    cudaGetSymbolAddress((void**)&WkT,    g_WkT);
    cudaGetSymbolAddress((void**)&WvT,    g_WvT);
    cudaGetSymbolAddress((void**)&WoT,    g_WoT);
    cudaGetSymbolAddress((void**)&Wf1T,   g_Wf1T);
    cudaGetSymbolAddress((void**)&Wf2T,   g_Wf2T);

    cudaFuncSetAttribute(tgemm_kernel, cudaFuncAttributeMaxDynamicSharedMemorySize, TG_SMEM_BYTES);

    dim3 tb(32, 8);
    dim3 tg768 (D_MOD / 128, S_LEN / 128);   // (6, 32)
    dim3 tg3072(FF_DIM / 128, S_LEN / 128);  // (24, 32)

    // Launch order puts the first tgemm at global launch index 5 so the
    // ncu capture (-s 5 -c 1) profiles the GEMM instead of a transpose.
    transpose_kernel<<<dim3(D_MOD/32, D_MOD/32, N_LAYER), tb>>>(Wq, WqT, D_MOD, D_MOD);   // 0
    transpose_kernel<<<dim3(D_MOD/32, D_MOD/32, N_LAYER), tb>>>(Wk, WkT, D_MOD, D_MOD);   // 1
    transpose_kernel<<<dim3(D_MOD/32, D_MOD/32, N_LAYER), tb>>>(Wv, WvT, D_MOD, D_MOD);   // 2
    embed_kernel<<<S_LEN, 256>>>(ids, wemb, pemb, x);                                     // 3
    ln_kernel<<<S_LEN, 256>>>(x, nullptr, emb_g, emb_b, xr);                              // 4
    tgemm_kernel<<<tg768, 256, TG_SMEM_BYTES>>>(xr, WqT, bq, q, S_LEN, D_MOD, D_MOD, 1);  // 5 <- ncu
    transpose_kernel<<<dim3(D_MOD/32, D_MOD/32, N_LAYER), tb>>>(Wo,   WoT,  D_MOD, D_MOD);
    transpose_kernel<<<dim3(FF_DIM/32, D_MOD/32, N_LAYER), tb>>>(Wff1, Wf1T, D_MOD, FF_DIM);
    transpose_kernel<<<dim3(D_MOD/32, FF_DIM/32, N_LAYER), tb>>>(Wff2, Wf2T, FF_DIM, D_MOD);

    for (int l = 0; l < N_LAYER; l++) {
        const float* WqT_l  = WqT  + (size_t)l * D_MOD * D_MOD;
        const float* WkT_l  = WkT  + (size_t)l * D_MOD * D_MOD;
        const float* WvT_l  = WvT  + (size_t)l * D_MOD * D_MOD;
        const float* WoT_l  = WoT  + (size_t)l * D_MOD * D_MOD;
        const float* Wf1T_l = Wf1T + (size_t)l * D_MOD * FF_DIM;
        const float* Wf2T_l = Wf2T + (size_t)l * FF_DIM * D_MOD;

        if (l > 0)
            tgemm_kernel<<<tg768, 256, TG_SMEM_BYTES>>>(xr, WqT_l, bq + l * D_MOD, q, S_LEN, D_MOD, D_MOD, 1);
        tgemm_kernel<<<tg768, 256, TG_SMEM_BYTES>>>(xr, WkT_l, bk + l * D_MOD, k, S_LEN, D_MOD, D_MOD, 0);
        tgemm_kernel<<<tg768, 256, TG_SMEM_BYTES>>>(xr, WvT_l, bv + l * D_MOD, v, S_LEN, D_MOD, D_MOD, 0);

        attn_kernel<<<dim3(S_LEN / QB, N_HEAD), 256>>>(q, k, v, mask, a);

        tgemm_kernel<<<tg768, 256, TG_SMEM_BYTES>>>(a, WoT_l, bo + l * D_MOD, o, S_LEN, D_MOD, D_MOD, 0);
        ln_kernel<<<S_LEN, 256>>>(x, o, ln1_g + l * D_MOD, ln1_b + l * D_MOD, xr);

        tgemm_kernel<<<tg3072, 256, TG_SMEM_BYTES>>>(xr, Wf1T_l, bff1 + l * FF_DIM, ff, S_LEN, FF_DIM, D_MOD, 2);
        tgemm_kernel<<<tg768,  256, TG_SMEM_BYTES>>>(ff, Wf2T_l, bff2 + l * D_MOD, o, S_LEN, D_MOD, FF_DIM, 0);
        ln_kernel<<<S_LEN, 256>>>(x, o, ln2_g + l * D_MOD, ln2_b + l * D_MOD, xr);
    }

    zero_pooled_kernel<<<1, 256>>>(pooled);
    msum_kernel<<<1, 256>>>(mask, msum);
    pool_kernel<<<S_LEN / 256, 256>>>(x, mask, pooled);
    head1_kernel<<<1, 512>>>(pooled, W1, b1, msum, h1);
    head2_kernel<<<1, 256>>>(h1, W2, b2, h2);
    head3_kernel<<<1, 256>>>(h2, W3, b3, out, out_size);
}

// round 12
// speedup vs baseline: 2.5385x; 1.2471x over previous
#include <cuda_runtime.h>
#include <cuda_fp16.h>
#include <math.h>
#include <stdint.h>

#define S_LEN 4096
#define D_MOD 768
#define N_HEAD 12
#define DH 64
#define N_LAYER 4
#define FF_DIM 3072
#define WIN 256

// ---------------- scratch (device globals; no allocation) ----------------
__device__ float  g_x  [S_LEN * D_MOD];
__device__ __half g_xr [S_LEN * D_MOD];          // fp16 copy of x (GEMM A)
__device__ float  g_qkv[S_LEN * 3 * D_MOD];      // fused q|k|v, fp32
__device__ __half g_a  [S_LEN * D_MOD];          // attention out (fp16, feeds O GEMM)
__device__ float  g_o  [S_LEN * D_MOD];
__device__ __half g_ff [S_LEN * FF_DIM];         // FF1 out (fp16, feeds FF2)
__device__ float  g_pooled[D_MOD];
__device__ float  g_h1[512];
__device__ float  g_h2[256];
__device__ float  g_msum[1];
// fp16 transposed weights [N][K]
__device__ __half g_qkvT[N_LAYER * 3 * D_MOD * D_MOD];
__device__ __half g_WoT [N_LAYER * D_MOD * D_MOD];
__device__ __half g_f1T [N_LAYER * D_MOD * FF_DIM];
__device__ __half g_f2T [N_LAYER * FF_DIM * D_MOD];
__device__ float  g_bqkv[N_LAYER * 3 * D_MOD];

__device__ __forceinline__ void mma_f16(float* d, const uint32_t* a, const uint32_t* b) {
    asm volatile(
        "mma.sync.aligned.m16n8k16.row.col.f32.f16.f16.f32 "
        "{%0,%1,%2,%3}, {%4,%5,%6,%7}, {%8,%9}, {%0,%1,%2,%3};\n"
        : "+f"(d[0]), "+f"(d[1]), "+f"(d[2]), "+f"(d[3])
        : "r"(a[0]), "r"(a[1]), "r"(a[2]), "r"(a[3]), "r"(b[0]), "r"(b[1]));
}

__device__ __forceinline__ void cp_async16(uint32_t saddr, const void* g) {
    asm volatile("cp.async.cg.shared.global [%0], [%1], 16;" :: "r"(saddr), "l"(g) : "memory");
}
#define CP_COMMIT() asm volatile("cp.async.commit_group;" ::: "memory")
#define CP_WAIT1()  asm volatile("cp.async.wait_group 1;" ::: "memory")
#define CP_WAIT0()  asm volatile("cp.async.wait_group 0;" ::: "memory")

// ---------------- unified weight prep: transpose + fp16 + bias fuse --------
// Tile ranges: [0,6912) qkv, [6912,9216) Wo, [9216,18432) ff1, [18432,27648) ff2,
// [27648,27652) bias-fuse per layer.
__global__ void prep_kernel(const float* __restrict__ Wq, const float* __restrict__ Wk,
                            const float* __restrict__ Wv, const float* __restrict__ Wo,
                            const float* __restrict__ Wff1, const float* __restrict__ Wff2,
                            const float* __restrict__ bq, const float* __restrict__ bk,
                            const float* __restrict__ bv,
                            __half* __restrict__ qkvT, __half* __restrict__ WoT,
                            __half* __restrict__ f1T, __half* __restrict__ f2T,
                            float* __restrict__ bqkv)
{
    int t = blockIdx.x;
    int tx = threadIdx.x, ty = threadIdx.y;
    if (t >= 27648) {
        int layer = t - 27648;
        int flat = ty * 32 + tx;
        for (int i = flat; i < D_MOD; i += 256) {
            bqkv[layer * 3 * D_MOD + i]             = bq[layer * D_MOD + i];
            bqkv[layer * 3 * D_MOD + D_MOD + i]     = bk[layer * D_MOD + i];
            bqkv[layer * 3 * D_MOD + 2 * D_MOD + i] = bv[layer * D_MOD + i];
        }
        return;
    }
    const float* src; __half* dst; int K, N, k0, n0;
    if (t < 6912) {
        int part = t / 2304, r = t % 2304;
        int layer = r / 576, tile = r % 576;
        K = 768; N = 768;
        src = (part == 0 ? Wq : (part == 1 ? Wk : Wv)) + (size_t)layer * 768 * 768;
        dst = qkvT + (size_t)layer * 3 * 768 * 768 + (size_t)part * 768 * 768;
        k0 = (tile / 24) * 32; n0 = (tile % 24) * 32;
    } else if (t < 9216) {
        int r = t - 6912, layer = r / 576, tile = r % 576;
        K = 768; N = 768;
        src = Wo + (size_t)layer * 768 * 768;
        dst = WoT + (size_t)layer * 768 * 768;
        k0 = (tile / 24) * 32; n0 = (tile % 24) * 32;
    } else if (t < 18432) {
        int r = t - 9216, layer = r / 2304, tile = r % 2304;
        K = 768; N = 3072;
        src = Wff1 + (size_t)layer * 768 * 3072;
        dst = f1T + (size_t)layer * 768 * 3072;
        k0 = (tile / 96) * 32; n0 = (tile % 96) * 32;
    } else {
        int r = t - 18432, layer = r / 2304, tile = r % 2304;
        K = 3072; N = 768;
        src = Wff2 + (size_t)layer * 3072 * 768;
        dst = f2T + (size_t)layer * 3072 * 768;
        k0 = (tile / 24) * 32; n0 = (tile % 24) * 32;
    }
    __shared__ float tl[32][33];
#pragma unroll
    for (int i = 0; i < 32; i += 8)
        tl[ty + i][tx] = src[(size_t)(k0 + ty + i) * N + n0 + tx];
    __syncthreads();
#pragma unroll
    for (int i = 0; i < 32; i += 8)
        dst[(size_t)(n0 + ty + i) * K + k0 + tx] = __float2half_rn(tl[tx][ty + i]);
}

// ---------------- fp16 mma.sync GEMM, cp.async 3-stage pipeline ------------
// C[M,N] = A[M,K] @ Bt[N,K]^T + bias
// epi: 0 = bias, write f32 | 2 = bias+GELU, write fp16 | 3 = QKV fused
//      (bias[global col]; scale 0.125 iff col<768; write f32)
#define PAD_H 72
#define TGH_TILE (128 * PAD_H)
#define TGH_STAGES 3
#define TGH_SMEM_BYTES (TGH_STAGES * 2 * TGH_TILE * 2)

__device__ __forceinline__ void tg_copy_h(const __half* __restrict__ Ab,
                                          const __half* __restrict__ Bb,
                                          int K, int k0,
                                          __half* sA, __half* sB, int tid)
{
#pragma unroll
    for (int i = 0; i < 4; i++) {
        int idx = tid + i * 256;           // 0..1023
        int row = idx >> 3, seg = idx & 7; // 8 halves per seg
        uint32_t da = (uint32_t)__cvta_generic_to_shared(sA + row * PAD_H + seg * 8);
        uint32_t db = (uint32_t)__cvta_generic_to_shared(sB + row * PAD_H + seg * 8);
        cp_async16(da, Ab + (size_t)row * K + k0 + seg * 8);
        cp_async16(db, Bb + (size_t)row * K + k0 + seg * 8);
    }
}

__global__ void __launch_bounds__(256, 2) tgemm_kernel(const __half* __restrict__ A,
                                                       const __half* __restrict__ Bt,
                                                       const float* __restrict__ bias,
                                                       void* __restrict__ Cout,
                                                       int M, int N, int K, int epi)
{
    extern __shared__ __half smh[];
    __half* sA = smh;
    __half* sB = smh + TGH_STAGES * TGH_TILE;

    const int tid  = threadIdx.x;
    const int wid  = tid >> 5;
    const int lane = tid & 31;
    const int wm   = wid & 1;
    const int wn   = wid >> 1;
    const int g    = lane >> 2;
    const int cq2  = (lane & 3) * 2;
    const int m0 = blockIdx.y * 128;
    const int n0 = blockIdx.x * 128;
    const int NC = K >> 6;

    const __half* Ab = A  + (size_t)m0 * K;
    const __half* Bb = Bt + (size_t)n0 * K;

    float acc[4][4][4];
#pragma unroll
    for (int i = 0; i < 4; i++)
#pragma unroll
        for (int j = 0; j < 4; j++)
#pragma unroll
            for (int r = 0; r < 4; r++) acc[i][j][r] = 0.f;

    tg_copy_h(Ab, Bb, K, 0,  sA,            sB,            tid); CP_COMMIT();
    tg_copy_h(Ab, Bb, K, 64, sA + TGH_TILE, sB + TGH_TILE, tid); CP_COMMIT();

    int st = 0;
    for (int c = 0; c < NC; c++) {
        if (c + 1 < NC) { CP_WAIT1(); } else { CP_WAIT0(); }
        __syncthreads();
        if (c + 2 < NC) {
            int ns = st + 2; if (ns >= TGH_STAGES) ns -= TGH_STAGES;
            tg_copy_h(Ab, Bb, K, (c + 2) << 6, sA + ns * TGH_TILE, sB + ns * TGH_TILE, tid);
            CP_COMMIT();
        }
        const __half* cA = sA + st * TGH_TILE;
        const __half* cB = sB + st * TGH_TILE;
#pragma unroll
        for (int kk = 0; kk < 4; kk++) {
            const int kb = kk * 16;
            uint32_t af[4][4], bf[4][2];
#pragma unroll
            for (int mt = 0; mt < 4; mt++) {
                int r = wm * 64 + mt * 16 + g;
                af[mt][0] = *(const uint32_t*)&cA[(size_t)r       * PAD_H + kb + cq2];
                af[mt][1] = *(const uint32_t*)&cA[(size_t)(r + 8) * PAD_H + kb + cq2];
                af[mt][2] = *(const uint32_t*)&cA[(size_t)r       * PAD_H + kb + 8 + cq2];
                af[mt][3] = *(const uint32_t*)&cA[(size_t)(r + 8) * PAD_H + kb + 8 + cq2];
            }
#pragma unroll
            for (int nt = 0; nt < 4; nt++) {
                int nr = wn * 32 + nt * 8 + g;
                bf[nt][0] = *(const uint32_t*)&cB[(size_t)nr * PAD_H + kb + cq2];
                bf[nt][1] = *(const uint32_t*)&cB[(size_t)nr * PAD_H + kb + 8 + cq2];
            }
#pragma unroll
            for (int mt = 0; mt < 4; mt++)
#pragma unroll
                for (int nt = 0; nt < 4; nt++)
                    mma_f16(acc[mt][nt], af[mt], bf[nt]);
        }
        st++; if (st >= TGH_STAGES) st = 0;
    }

    // ---- epilogue
    const bool qscale = (epi == 3) && (n0 < 768);
    float* Cf = (float*)Cout;
    __half* Ch = (__half*)Cout;
#pragma unroll
    for (int mt = 0; mt < 4; mt++) {
        int row = m0 + wm * 64 + mt * 16 + g;
#pragma unroll
        for (int nt = 0; nt < 4; nt++) {
            int col = n0 + wn * 32 + nt * 8 + cq2;
            float bb0 = bias[col], bb1 = bias[col + 1];
            float v0 = acc[mt][nt][0] + bb0;
            float v1 = acc[mt][nt][1] + bb1;
            float v2 = acc[mt][nt][2] + bb0;
            float v3 = acc[mt][nt][3] + bb1;
            if (qscale) { v0 *= 0.125f; v1 *= 0.125f; v2 *= 0.125f; v3 *= 0.125f; }
            if (epi == 2) {
                v0 = 0.5f * v0 * (1.0f + erff(v0 * 0.70710678118654752f));
                v1 = 0.5f * v1 * (1.0f + erff(v1 * 0.70710678118654752f));
                v2 = 0.5f * v2 * (1.0f + erff(v2 * 0.70710678118654752f));
                v3 = 0.5f * v3 * (1.0f + erff(v3 * 0.70710678118654752f));
                *(__half2*)(Ch + (size_t)row * N + col)       = __floats2half2_rn(v0, v1);
                *(__half2*)(Ch + (size_t)(row + 8) * N + col) = __floats2half2_rn(v2, v3);
            } else {
                *(float2*)(Cf + (size_t)row * N + col)       = make_float2(v0, v1);
                *(float2*)(Cf + (size_t)(row + 8) * N + col) = make_float2(v2, v3);
            }
        }
    }
}

// ---------------- embedding ----------------
__global__ void embed_kernel(const int* __restrict__ ids,
                             const float* __restrict__ wemb,
                             const float* __restrict__ pemb,
                             float* __restrict__ X)
{
    int row = blockIdx.x;
    int id  = ids[row];
    const float* wp = wemb + (size_t)id * D_MOD;
    const float* pp = pemb + (size_t)row * D_MOD;
    float* xp = X + (size_t)row * D_MOD;
    for (int d = threadIdx.x; d < D_MOD; d += blockDim.x)
        xp[d] = wp[d] + pp[d];
}

// -------- LayerNorm (optional residual), in-place on X; fp16 copy to XR ----
__global__ void __launch_bounds__(256) ln_kernel(float* __restrict__ X,
                                                 const float* __restrict__ Aadd,
                                                 const float* __restrict__ g,
                                                 const float* __restrict__ b,
                                                 __half* __restrict__ XR)
{
    int row = blockIdx.x;
    int tid = threadIdx.x;
    int lane = tid & 31, wid = tid >> 5;
    __shared__ float red[8];
    float vals[3];
    float s = 0.f;
    const size_t base = (size_t)row * D_MOD;
#pragma unroll
    for (int i = 0; i < 3; i++) {
        int d = tid + i * 256;
        float v = X[base + d];
        if (Aadd) v += Aadd[base + d];
        vals[i] = v;
        s += v;
    }
#pragma unroll
    for (int o = 16; o > 0; o >>= 1) s += __shfl_xor_sync(0xFFFFFFFFu, s, o);
    if (lane == 0) red[wid] = s;
    __syncthreads();
    float tot = red[0] + red[1] + red[2] + red[3] + red[4] + red[5] + red[6] + red[7];
    float mean = tot * (1.0f / D_MOD);
    float ss = 0.f;
#pragma unroll
    for (int i = 0; i < 3; i++) { float dv = vals[i] - mean; ss += dv * dv; }
#pragma unroll
    for (int o = 16; o > 0; o >>= 1) ss += __shfl_xor_sync(0xFFFFFFFFu, ss, o);
    __syncthreads();
    if (lane == 0) red[wid] = ss;
    __syncthreads();
    float tot2 = red[0] + red[1] + red[2] + red[3] + red[4] + red[5] + red[6] + red[7];
    float rstd = rsqrtf(tot2 * (1.0f / D_MOD) + 1e-5f);
#pragma unroll
    for (int i = 0; i < 3; i++) {
        int d = tid + i * 256;
        float outv = (vals[i] - mean) * rstd * g[d] + b[d];
        X[base + d] = outv;
        XR[base + d] = __float2half_rn(outv);
    }
}

// ---------------- band attention: split-D flash, 2 threads per query --------
// Reads fused qkv [S][2304] (q|k|v). Writes fp16 (feeds O-proj GEMM only).
#define QB 128
#define QKV_LD (3 * D_MOD)
__global__ void __launch_bounds__(256) attn_kernel(const float* __restrict__ QKV,
                                                   const int* __restrict__ mask,
                                                   __half* __restrict__ O)
{
    const int cb  = blockIdx.x;
    const int h   = blockIdx.y;
    const int tid = threadIdx.x;
    const int qi   = tid >> 1;
    const int half = tid & 1;
    const int lane = tid & 31;
    const unsigned pair_mask = 0x3u << (lane & 30);
    const int sq = cb * QB + qi;

    __shared__ float ks[64][64];
    __shared__ float vs[64][64];
    __shared__ float mt[64];

    float qreg[32];
    const float* qp = QKV + (size_t)sq * QKV_LD + h * DH + half * 32;
#pragma unroll
    for (int i = 0; i < 8; i++) {
        float4 qv = *(const float4*)(qp + i * 4);
        qreg[i * 4 + 0] = qv.x; qreg[i * 4 + 1] = qv.y;
        qreg[i * 4 + 2] = qv.z; qreg[i * 4 + 3] = qv.w;
    }

    float m = -1e30f, l = 0.f;
    float acc[32];
#pragma unroll
    for (int d = 0; d < 32; d++) acc[d] = 0.f;

    int lo = sq - WIN; if (lo < 0) lo = 0;
    int hi = sq + WIN; if (hi > S_LEN - 1) hi = S_LEN - 1;
    const int base = cb * QB - WIN;
    int blo = base;           if (blo < 0) blo = 0;
    int bhi = base + QB - 1 + 2 * WIN; if (bhi > S_LEN - 1) bhi = S_LEN - 1;

    for (int t = 0; t < (QB + 2 * WIN) / 64; t++) {
        int tstart = base + t * 64;
        if (tstart + 63 < blo || tstart > bhi) continue;
        __syncthreads();
#pragma unroll
        for (int i = 0; i < 4; i++) {
            int e  = tid + i * 256;
            int jj = e >> 4, d4 = (e & 15) * 4;
            int g2 = tstart + jj;
            float4 kv = make_float4(0.f, 0.f, 0.f, 0.f);
            float4 vv = kv;
            if (g2 >= 0 && g2 < S_LEN) {
                size_t off = (size_t)g2 * QKV_LD + h * DH + d4;
                kv = *(const float4*)(QKV + off + D_MOD);
                vv = *(const float4*)(QKV + off + 2 * D_MOD);
            }
            *(float4*)&ks[jj][d4] = kv;
            *(float4*)&vs[jj][d4] = vv;
        }
        if (tid < 64) {
            int g2 = tstart + tid;
            mt[tid] = (g2 >= 0 && g2 < S_LEN && mask[g2] != 0) ? 1.f : 0.f;
        }
        __syncthreads();
        int j0 = lo - tstart; if (j0 < 0) j0 = 0;
        int j1 = hi - tstart; if (j1 > 63) j1 = 63;
        const int dc = half * 32;
        for (int jj = j0; jj <= j1; jj++) {
            if (mt[jj] == 0.f) continue;
            float part = 0.f;
#pragma unroll
            for (int d = 0; d < 32; d++) part += qreg[d] * ks[jj][dc + d];
            float other = __shfl_xor_sync(pair_mask, part, 1);
            float s = part + other;
            if (s <= m) {
                float p = __expf(s - m);
                l += p;
#pragma unroll
                for (int d = 0; d < 32; d++) acc[d] += p * vs[jj][dc + d];
            } else {
                float sc = __expf(m - s);
                l = l * sc + 1.0f;
#pragma unroll
                for (int d = 0; d < 32; d++) acc[d] = acc[d] * sc + vs[jj][dc + d];
                m = s;
            }
        }
    }
    float inv = 1.0f / l;
    __half* op = O + (size_t)sq * D_MOD + h * DH + half * 32;
#pragma unroll
    for (int i = 0; i < 16; i++)
        *(__half2*)(op + i * 2) = __floats2half2_rn(acc[i * 2] * inv, acc[i * 2 + 1] * inv);
}

// ---------------- pooling + head ----------------
__global__ void zero_pooled_kernel(float* __restrict__ pooled)
{
    for (int d = threadIdx.x; d < D_MOD; d += blockDim.x) pooled[d] = 0.f;
}

__global__ void msum_kernel(const int* __restrict__ mask, float* __restrict__ out)
{
    __shared__ float red[256];
    int tid = threadIdx.x;
    float s = 0.f;
    for (int i = tid; i < S_LEN; i += 256) s += (float)mask[i];
    red[tid] = s; __syncthreads();
    for (int o = 128; o > 0; o >>= 1) { if (tid < o) red[tid] += red[tid + o]; __syncthreads(); }
    if (tid == 0) out[0] = fmaxf(red[0], 1e-9f);
}

__global__ void __launch_bounds__(256) pool_kernel(const float* __restrict__ X,
                                                   const int* __restrict__ mask,
                                                   float* __restrict__ pooled)
{
    int s0 = blockIdx.x * 256;
    int tid = threadIdx.x;
    float a0 = 0.f, a1 = 0.f, a2 = 0.f;
    for (int r = 0; r < 256; r++) {
        float mf = (float)mask[s0 + r];
        const float* xp = X + (size_t)(s0 + r) * D_MOD;
        a0 += xp[tid]       * mf;
        a1 += xp[tid + 256] * mf;
        a2 += xp[tid + 512] * mf;
    }
    atomicAdd(&pooled[tid],       a0);
    atomicAdd(&pooled[tid + 256], a1);
    atomicAdd(&pooled[tid + 512], a2);
}

__global__ void head1_kernel(const float* __restrict__ pooled,
                             const float* __restrict__ W1, const float* __restrict__ b1,
                             const float* __restrict__ msum, float* __restrict__ h1)
{
    int i = threadIdx.x;
    float inv = 1.0f / msum[0];
    float dot = 0.f;
    for (int d = 0; d < D_MOD; d++) dot += pooled[d] * W1[(size_t)d * 512 + i];
    h1[i] = fmaxf(dot * inv + b1[i], 0.f);
}

__global__ void head2_kernel(const float* __restrict__ h1,
                             const float* __restrict__ W2, const float* __restrict__ b2,
                             float* __restrict__ h2)
{
    int i = threadIdx.x;
    if (i < 250) {
        float dot = 0.f;
        for (int d = 0; d < 512; d++) dot += h1[d] * W2[(size_t)d * 250 + i];
        h2[i] = fmaxf(dot + b2[i], 0.f);
    } else if (i < 256) {
        h2[i] = 0.f;
    }
}

__global__ void head3_kernel(const float* __restrict__ h2,
                             const float* __restrict__ W3, const float* __restrict__ b3,
                             float* __restrict__ out, int out_size)
{
    __shared__ float red[256];
    __shared__ float pred;
    int tid = threadIdx.x;
    float v = (tid < 250) ? h2[tid] * W3[tid] : 0.f;
    red[tid] = v; __syncthreads();
    for (int o = 128; o > 0; o >>= 1) { if (tid < o) red[tid] += red[tid + o]; __syncthreads(); }
    if (tid == 0) pred = red[0] + b3[0];
    __syncthreads();
    for (int i = tid; i < out_size; i += 256) out[i] = pred;
}

// ---------------- launch ----------------
extern "C" void kernel_launch(void* const* d_in, const int* in_sizes, int n_in,
                              void* d_out, int out_size)
{
    const int*   ids    = (const int*)  d_in[0];
    const int*   mask   = (const int*)  d_in[1];
    const float* wemb   = (const float*)d_in[2];
    const float* pemb   = (const float*)d_in[3];
    const float* emb_g  = (const float*)d_in[4];
    const float* emb_b  = (const float*)d_in[5];
    const float* Wq     = (const float*)d_in[6];
    const float* Wk     = (const float*)d_in[7];
    const float* Wv     = (const float*)d_in[8];
    const float* Wo     = (const float*)d_in[9];
    const float* bq     = (const float*)d_in[10];
    const float* bk     = (const float*)d_in[11];
    const float* bv     = (const float*)d_in[12];
    const float* bo     = (const float*)d_in[13];
    const float* ln1_g  = (const float*)d_in[14];
    const float* ln1_b  = (const float*)d_in[15];
    const float* Wff1   = (const float*)d_in[16];
    const float* bff1   = (const float*)d_in[17];
    const float* Wff2   = (const float*)d_in[18];
    const float* bff2   = (const float*)d_in[19];
    const float* ln2_g  = (const float*)d_in[20];
    const float* ln2_b  = (const float*)d_in[21];
    const float* W1     = (const float*)d_in[22];
    const float* b1     = (const float*)d_in[23];
    const float* W2     = (const float*)d_in[24];
    const float* b2     = (const float*)d_in[25];
    const float* W3     = (const float*)d_in[26];
    const float* b3     = (const float*)d_in[27];
    float* out = (float*)d_out;

    float *x, *qkv, *o, *pooled, *h1, *h2, *msum, *bqkv;
    __half *xr, *a, *ff, *qkvT, *WoT, *f1T, *f2T;
    cudaGetSymbolAddress((void**)&x,      g_x);
    cudaGetSymbolAddress((void**)&xr,     g_xr);
    cudaGetSymbolAddress((void**)&qkv,    g_qkv);
    cudaGetSymbolAddress((void**)&a,      g_a);
    cudaGetSymbolAddress((void**)&o,      g_o);
    cudaGetSymbolAddress((void**)&ff,     g_ff);
    cudaGetSymbolAddress((void**)&pooled, g_pooled);
    cudaGetSymbolAddress((void**)&h1,     g_h1);
    cudaGetSymbolAddress((void**)&h2,     g_h2);
    cudaGetSymbolAddress((void**)&msum,   g_msum);
    cudaGetSymbolAddress((void**)&qkvT,   g_qkvT);
    cudaGetSymbolAddress((void**)&WoT,    g_WoT);
    cudaGetSymbolAddress((void**)&f1T,    g_f1T);
    cudaGetSymbolAddress((void**)&f2T,    g_f2T);
    cudaGetSymbolAddress((void**)&bqkv,   g_bqkv);

    cudaFuncSetAttribute(tgemm_kernel, cudaFuncAttributeMaxDynamicSharedMemorySize, TGH_SMEM_BYTES);

    dim3 tgQKV(3 * D_MOD / 128, S_LEN / 128);   // (18, 32)
    dim3 tg768 (D_MOD / 128, S_LEN / 128);      // (6, 32)
    dim3 tg3072(FF_DIM / 128, S_LEN / 128);     // (24, 32)

    // 0: prep, 1: embed, 2: ln, 3: QKV gemm, 4: attn, 5: O gemm (<- ncu -s 5)
    prep_kernel<<<27652, dim3(32, 8)>>>(Wq, Wk, Wv, Wo, Wff1, Wff2, bq, bk, bv,
                                        qkvT, WoT, f1T, f2T, bqkv);
    embed_kernel<<<S_LEN, 256>>>(ids, wemb, pemb, x);
    ln_kernel<<<S_LEN, 256>>>(x, nullptr, emb_g, emb_b, xr);

    for (int l = 0; l < N_LAYER; l++) {
        const __half* qkvT_l = qkvT + (size_t)l * 3 * D_MOD * D_MOD;
        const __half* WoT_l  = WoT  + (size_t)l * D_MOD * D_MOD;
        const __half* f1T_l  = f1T  + (size_t)l * D_MOD * FF_DIM;
        const __half* f2T_l  = f2T  + (size_t)l * FF_DIM * D_MOD;
        const float*  bqkv_l = bqkv + (size_t)l * 3 * D_MOD;

        tgemm_kernel<<<tgQKV, 256, TGH_SMEM_BYTES>>>(xr, qkvT_l, bqkv_l, qkv,
                                                     S_LEN, 3 * D_MOD, D_MOD, 3);
        attn_kernel<<<dim3(S_LEN / QB, N_HEAD), 256>>>(qkv, mask, a);
        tgemm_kernel<<<tg768, 256, TGH_SMEM_BYTES>>>(a, WoT_l, bo + l * D_MOD, o,
                                                     S_LEN, D_MOD, D_MOD, 0);
        ln_kernel<<<S_LEN, 256>>>(x, o, ln1_g + l * D_MOD, ln1_b + l * D_MOD, xr);

        tgemm_kernel<<<tg3072, 256, TGH_SMEM_BYTES>>>(xr, f1T_l, bff1 + l * FF_DIM, ff,
                                                      S_LEN, FF_DIM, D_MOD, 2);
        tgemm_kernel<<<tg768, 256, TGH_SMEM_BYTES>>>(ff, f2T_l, bff2 + l * D_MOD, o,
                                                     S_LEN, D_MOD, FF_DIM, 0);
        ln_kernel<<<S_LEN, 256>>>(x, o, ln2_g + l * D_MOD, ln2_b + l * D_MOD, xr);
    }

    zero_pooled_kernel<<<1, 256>>>(pooled);
    msum_kernel<<<1, 256>>>(mask, msum);
    pool_kernel<<<S_LEN / 256, 256>>>(x, mask, pooled);
    head1_kernel<<<1, 512>>>(pooled, W1, b1, msum, h1);
    head2_kernel<<<1, 256>>>(h1, W2, b2, h2);
    head3_kernel<<<1, 256>>>(h2, W3, b3, out, out_size);
}

// round 13
// speedup vs baseline: 7.7516x; 3.0536x over previous
#include <cuda_runtime.h>
#include <cuda_fp16.h>
#include <math.h>
#include <stdint.h>

#define S_LEN 4096
#define D_MOD 768
#define N_HEAD 12
#define DH 64
#define N_LAYER 4
#define FF_DIM 3072
#define WIN 256

// ---------------- scratch (device globals; no allocation) ----------------
__device__ float  g_x  [S_LEN * D_MOD];
__device__ __half g_xr [S_LEN * D_MOD];          // fp16 copy of x (GEMM A)
__device__ __half g_qkvh[3 * S_LEN * D_MOD];     // q|k|v fp16, sectioned [sec][S][768]
__device__ __half g_a  [S_LEN * D_MOD];          // attention out (fp16)
__device__ float  g_o  [S_LEN * D_MOD];
__device__ __half g_ff [S_LEN * FF_DIM];         // FF1 out (fp16)
__device__ float  g_pooled[D_MOD];
__device__ float  g_h1[512];
__device__ float  g_h2[256];
__device__ float  g_msum[1];
// fp16 transposed weights [N][K]
__device__ __half g_qkvT[N_LAYER * 3 * D_MOD * D_MOD];
__device__ __half g_WoT [N_LAYER * D_MOD * D_MOD];
__device__ __half g_f1T [N_LAYER * D_MOD * FF_DIM];
__device__ __half g_f2T [N_LAYER * FF_DIM * D_MOD];
__device__ float  g_bqkv[N_LAYER * 3 * D_MOD];

__device__ __forceinline__ void mma_f16(float* d, const uint32_t* a, const uint32_t* b) {
    asm volatile(
        "mma.sync.aligned.m16n8k16.row.col.f32.f16.f16.f32 "
        "{%0,%1,%2,%3}, {%4,%5,%6,%7}, {%8,%9}, {%0,%1,%2,%3};\n"
        : "+f"(d[0]), "+f"(d[1]), "+f"(d[2]), "+f"(d[3])
        : "r"(a[0]), "r"(a[1]), "r"(a[2]), "r"(a[3]), "r"(b[0]), "r"(b[1]));
}

__device__ __forceinline__ void cp_async16(uint32_t saddr, const void* g) {
    asm volatile("cp.async.cg.shared.global [%0], [%1], 16;" :: "r"(saddr), "l"(g) : "memory");
}
#define CP_COMMIT() asm volatile("cp.async.commit_group;" ::: "memory")
#define CP_WAIT1()  asm volatile("cp.async.wait_group 1;" ::: "memory")
#define CP_WAIT0()  asm volatile("cp.async.wait_group 0;" ::: "memory")

// ---------------- unified weight prep: transpose + fp16 + bias fuse --------
__global__ void prep_kernel(const float* __restrict__ Wq, const float* __restrict__ Wk,
                            const float* __restrict__ Wv, const float* __restrict__ Wo,
                            const float* __restrict__ Wff1, const float* __restrict__ Wff2,
                            const float* __restrict__ bq, const float* __restrict__ bk,
                            const float* __restrict__ bv,
                            __half* __restrict__ qkvT, __half* __restrict__ WoT,
                            __half* __restrict__ f1T, __half* __restrict__ f2T,
                            float* __restrict__ bqkv)
{
    int t = blockIdx.x;
    int tx = threadIdx.x, ty = threadIdx.y;
    if (t >= 27648) {
        int layer = t - 27648;
        int flat = ty * 32 + tx;
        for (int i = flat; i < D_MOD; i += 256) {
            bqkv[layer * 3 * D_MOD + i]             = bq[layer * D_MOD + i];
            bqkv[layer * 3 * D_MOD + D_MOD + i]     = bk[layer * D_MOD + i];
            bqkv[layer * 3 * D_MOD + 2 * D_MOD + i] = bv[layer * D_MOD + i];
        }
        return;
    }
    const float* src; __half* dst; int K, N, k0, n0;
    if (t < 6912) {
        int part = t / 2304, r = t % 2304;
        int layer = r / 576, tile = r % 576;
        K = 768; N = 768;
        src = (part == 0 ? Wq : (part == 1 ? Wk : Wv)) + (size_t)layer * 768 * 768;
        dst = qkvT + (size_t)layer * 3 * 768 * 768 + (size_t)part * 768 * 768;
        k0 = (tile / 24) * 32; n0 = (tile % 24) * 32;
    } else if (t < 9216) {
        int r = t - 6912, layer = r / 576, tile = r % 576;
        K = 768; N = 768;
        src = Wo + (size_t)layer * 768 * 768;
        dst = WoT + (size_t)layer * 768 * 768;
        k0 = (tile / 24) * 32; n0 = (tile % 24) * 32;
    } else if (t < 18432) {
        int r = t - 9216, layer = r / 2304, tile = r % 2304;
        K = 768; N = 3072;
        src = Wff1 + (size_t)layer * 768 * 3072;
        dst = f1T + (size_t)layer * 768 * 3072;
        k0 = (tile / 96) * 32; n0 = (tile % 96) * 32;
    } else {
        int r = t - 18432, layer = r / 2304, tile = r % 2304;
        K = 3072; N = 768;
        src = Wff2 + (size_t)layer * 3072 * 768;
        dst = f2T + (size_t)layer * 3072 * 768;
        k0 = (tile / 24) * 32; n0 = (tile % 24) * 32;
    }
    __shared__ float tl[32][33];
#pragma unroll
    for (int i = 0; i < 32; i += 8)
        tl[ty + i][tx] = src[(size_t)(k0 + ty + i) * N + n0 + tx];
    __syncthreads();
#pragma unroll
    for (int i = 0; i < 32; i += 8)
        dst[(size_t)(n0 + ty + i) * K + k0 + tx] = __float2half_rn(tl[tx][ty + i]);
}

// ---------------- fp16 mma.sync GEMM, cp.async 3-stage pipeline ------------
// epi: 0 = bias, f32 out | 2 = bias+GELU, fp16 out | 3 = QKV fused:
//      sections q(scaled)/k/v fp16 at Cout + sec*S*768
#define PAD_H 72
#define TGH_TILE (128 * PAD_H)
#define TGH_STAGES 3
#define TGH_SMEM_BYTES (TGH_STAGES * 2 * TGH_TILE * 2)

__device__ __forceinline__ void tg_copy_h(const __half* __restrict__ Ab,
                                          const __half* __restrict__ Bb,
                                          int K, int k0,
                                          __half* sA, __half* sB, int tid)
{
#pragma unroll
    for (int i = 0; i < 4; i++) {
        int idx = tid + i * 256;
        int row = idx >> 3, seg = idx & 7;
        uint32_t da = (uint32_t)__cvta_generic_to_shared(sA + row * PAD_H + seg * 8);
        uint32_t db = (uint32_t)__cvta_generic_to_shared(sB + row * PAD_H + seg * 8);
        cp_async16(da, Ab + (size_t)row * K + k0 + seg * 8);
        cp_async16(db, Bb + (size_t)row * K + k0 + seg * 8);
    }
}

__global__ void __launch_bounds__(256, 2) tgemm_kernel(const __half* __restrict__ A,
                                                       const __half* __restrict__ Bt,
                                                       const float* __restrict__ bias,
                                                       void* __restrict__ Cout,
                                                       int M, int N, int K, int epi)
{
    extern __shared__ __half smh[];
    __half* sA = smh;
    __half* sB = smh + TGH_STAGES * TGH_TILE;

    const int tid  = threadIdx.x;
    const int wid  = tid >> 5;
    const int lane = tid & 31;
    const int wm   = wid & 1;
    const int wn   = wid >> 1;
    const int g    = lane >> 2;
    const int cq2  = (lane & 3) * 2;
    const int m0 = blockIdx.y * 128;
    const int n0 = blockIdx.x * 128;
    const int NC = K >> 6;

    const __half* Ab = A  + (size_t)m0 * K;
    const __half* Bb = Bt + (size_t)n0 * K;

    float acc[4][4][4];
#pragma unroll
    for (int i = 0; i < 4; i++)
#pragma unroll
        for (int j = 0; j < 4; j++)
#pragma unroll
            for (int r = 0; r < 4; r++) acc[i][j][r] = 0.f;

    tg_copy_h(Ab, Bb, K, 0,  sA,            sB,            tid); CP_COMMIT();
    tg_copy_h(Ab, Bb, K, 64, sA + TGH_TILE, sB + TGH_TILE, tid); CP_COMMIT();

    int st = 0;
    for (int c = 0; c < NC; c++) {
        if (c + 1 < NC) { CP_WAIT1(); } else { CP_WAIT0(); }
        __syncthreads();
        if (c + 2 < NC) {
            int ns = st + 2; if (ns >= TGH_STAGES) ns -= TGH_STAGES;
            tg_copy_h(Ab, Bb, K, (c + 2) << 6, sA + ns * TGH_TILE, sB + ns * TGH_TILE, tid);
            CP_COMMIT();
        }
        const __half* cA = sA + st * TGH_TILE;
        const __half* cB = sB + st * TGH_TILE;
#pragma unroll
        for (int kk = 0; kk < 4; kk++) {
            const int kb = kk * 16;
            uint32_t af[4][4], bf[4][2];
#pragma unroll
            for (int mt = 0; mt < 4; mt++) {
                int r = wm * 64 + mt * 16 + g;
                af[mt][0] = *(const uint32_t*)&cA[(size_t)r       * PAD_H + kb + cq2];
                af[mt][1] = *(const uint32_t*)&cA[(size_t)(r + 8) * PAD_H + kb + cq2];
                af[mt][2] = *(const uint32_t*)&cA[(size_t)r       * PAD_H + kb + 8 + cq2];
                af[mt][3] = *(const uint32_t*)&cA[(size_t)(r + 8) * PAD_H + kb + 8 + cq2];
            }
#pragma unroll
            for (int nt = 0; nt < 4; nt++) {
                int nr = wn * 32 + nt * 8 + g;
                bf[nt][0] = *(const uint32_t*)&cB[(size_t)nr * PAD_H + kb + cq2];
                bf[nt][1] = *(const uint32_t*)&cB[(size_t)nr * PAD_H + kb + 8 + cq2];
            }
#pragma unroll
            for (int mt = 0; mt < 4; mt++)
#pragma unroll
                for (int nt = 0; nt < 4; nt++)
                    mma_f16(acc[mt][nt], af[mt], bf[nt]);
        }
        st++; if (st >= TGH_STAGES) st = 0;
    }

    // ---- epilogue
    const int sec = (epi == 3) ? (n0 / 768) : 0;
    const bool qsc = (epi == 3) && (sec == 0);
    __half* dsec = (__half*)Cout + (size_t)sec * S_LEN * 768;
    const int nb = n0 - sec * 768;
    float* Cf = (float*)Cout;
    __half* Ch = (__half*)Cout;
#pragma unroll
    for (int mt = 0; mt < 4; mt++) {
        int row = m0 + wm * 64 + mt * 16 + g;
#pragma unroll
        for (int nt = 0; nt < 4; nt++) {
            int colw = wn * 32 + nt * 8 + cq2;
            int col = n0 + colw;
            float bb0 = bias[col], bb1 = bias[col + 1];
            float v0 = acc[mt][nt][0] + bb0;
            float v1 = acc[mt][nt][1] + bb1;
            float v2 = acc[mt][nt][2] + bb0;
            float v3 = acc[mt][nt][3] + bb1;
            if (epi == 3) {
                if (qsc) { v0 *= 0.125f; v1 *= 0.125f; v2 *= 0.125f; v3 *= 0.125f; }
                int lcol = nb + colw;
                *(__half2*)(dsec + (size_t)row * 768 + lcol)       = __floats2half2_rn(v0, v1);
                *(__half2*)(dsec + (size_t)(row + 8) * 768 + lcol) = __floats2half2_rn(v2, v3);
            } else if (epi == 2) {
                v0 = 0.5f * v0 * (1.0f + erff(v0 * 0.70710678118654752f));
                v1 = 0.5f * v1 * (1.0f + erff(v1 * 0.70710678118654752f));
                v2 = 0.5f * v2 * (1.0f + erff(v2 * 0.70710678118654752f));
                v3 = 0.5f * v3 * (1.0f + erff(v3 * 0.70710678118654752f));
                *(__half2*)(Ch + (size_t)row * N + col)       = __floats2half2_rn(v0, v1);
                *(__half2*)(Ch + (size_t)(row + 8) * N + col) = __floats2half2_rn(v2, v3);
            } else {
                *(float2*)(Cf + (size_t)row * N + col)       = make_float2(v0, v1);
                *(float2*)(Cf + (size_t)(row + 8) * N + col) = make_float2(v2, v3);
            }
        }
    }
}

// ---------------- embedding ----------------
__global__ void embed_kernel(const int* __restrict__ ids,
                             const float* __restrict__ wemb,
                             const float* __restrict__ pemb,
                             float* __restrict__ X)
{
    int row = blockIdx.x;
    int id  = ids[row];
    const float* wp = wemb + (size_t)id * D_MOD;
    const float* pp = pemb + (size_t)row * D_MOD;
    float* xp = X + (size_t)row * D_MOD;
    for (int d = threadIdx.x; d < D_MOD; d += blockDim.x)
        xp[d] = wp[d] + pp[d];
}

// -------- LayerNorm (optional residual), in-place on X; fp16 copy to XR ----
__global__ void __launch_bounds__(256) ln_kernel(float* __restrict__ X,
                                                 const float* __restrict__ Aadd,
                                                 const float* __restrict__ g,
                                                 const float* __restrict__ b,
                                                 __half* __restrict__ XR)
{
    int row = blockIdx.x;
    int tid = threadIdx.x;
    int lane = tid & 31, wid = tid >> 5;
    __shared__ float red[8];
    float vals[3];
    float s = 0.f;
    const size_t base = (size_t)row * D_MOD;
#pragma unroll
    for (int i = 0; i < 3; i++) {
        int d = tid + i * 256;
        float v = X[base + d];
        if (Aadd) v += Aadd[base + d];
        vals[i] = v;
        s += v;
    }
#pragma unroll
    for (int o = 16; o > 0; o >>= 1) s += __shfl_xor_sync(0xFFFFFFFFu, s, o);
    if (lane == 0) red[wid] = s;
    __syncthreads();
    float tot = red[0] + red[1] + red[2] + red[3] + red[4] + red[5] + red[6] + red[7];
    float mean = tot * (1.0f / D_MOD);
    float ss = 0.f;
#pragma unroll
    for (int i = 0; i < 3; i++) { float dv = vals[i] - mean; ss += dv * dv; }
#pragma unroll
    for (int o = 16; o > 0; o >>= 1) ss += __shfl_xor_sync(0xFFFFFFFFu, ss, o);
    __syncthreads();
    if (lane == 0) red[wid] = ss;
    __syncthreads();
    float tot2 = red[0] + red[1] + red[2] + red[3] + red[4] + red[5] + red[6] + red[7];
    float rstd = rsqrtf(tot2 * (1.0f / D_MOD) + 1e-5f);
#pragma unroll
    for (int i = 0; i < 3; i++) {
        int d = tid + i * 256;
        float outv = (vals[i] - mean) * rstd * g[d] + b[d];
        X[base + d] = outv;
        XR[base + d] = __float2half_rn(outv);
    }
}

// ---------------- tensor-core band flash attention --------------------------
// CTA = 4 warps, 64 queries x 1 head. 9 aligned 64-key tiles; tiles 0/8 get
// triangular band masks. All mma fragment addressing mirrors tgemm_kernel.
#define APITCH 72
#define VPITCH 74
__global__ void __launch_bounds__(128) fattn_kernel(const __half* __restrict__ QKVh,
                                                    const int* __restrict__ mask,
                                                    __half* __restrict__ O)
{
    const __half* Qh = QKVh;
    const __half* Kh = QKVh + (size_t)S_LEN * D_MOD;
    const __half* Vh = QKVh + 2 * (size_t)S_LEN * D_MOD;

    const int qb = blockIdx.x;
    const int h  = blockIdx.y;
    const int qt0 = qb * 64;
    const int tid = threadIdx.x;
    const int w = tid >> 5, lane = tid & 31;
    const int g = lane >> 2, qd = lane & 3;

    __shared__ __align__(16) __half Qs[64][APITCH];
    __shared__ __align__(16) __half Ks[64][APITCH];
    __shared__ __align__(16) __half Vts[64][VPITCH];   // [d][key]
    __shared__ float mbias[64];

    // stage Q (coalesced: 8 threads x 16B per row)
    {
        int r = tid >> 3, seg = tid & 7;
#pragma unroll
        for (int p = 0; p < 4; p++) {
            int row = p * 16 + r;
            *(uint4*)&Qs[row][seg * 8] =
                *(const uint4*)(Qh + (size_t)(qt0 + row) * D_MOD + h * DH + seg * 8);
        }
    }
    __syncthreads();

    uint32_t qf[4][4];
    {
        int r0 = w * 16 + g;
#pragma unroll
        for (int kk = 0; kk < 4; kk++) {
            qf[kk][0] = *(const uint32_t*)&Qs[r0][kk * 16 + 2 * qd];
            qf[kk][1] = *(const uint32_t*)&Qs[r0 + 8][kk * 16 + 2 * qd];
            qf[kk][2] = *(const uint32_t*)&Qs[r0][kk * 16 + 8 + 2 * qd];
            qf[kk][3] = *(const uint32_t*)&Qs[r0 + 8][kk * 16 + 8 + 2 * qd];
        }
    }

    float oacc[8][4];
#pragma unroll
    for (int i = 0; i < 8; i++)
#pragma unroll
        for (int r = 0; r < 4; r++) oacc[i][r] = 0.f;
    float m0 = -1e30f, m1 = -1e30f, l0 = 0.f, l1 = 0.f;
    const int i_lo = w * 16 + g, i_hi = i_lo + 8;

    for (int t = 0; t < 9; t++) {
        const int kt0 = qt0 + (t - 4) * 64;
        if (kt0 < 0 || kt0 >= S_LEN) continue;
        __syncthreads();
        // stage K tile + V tile transposed
        {
            int r = tid >> 3, seg = tid & 7;
            bool odd = (r & 1) != 0;
#pragma unroll
            for (int p = 0; p < 4; p++) {
                int row = p * 16 + r;
                *(uint4*)&Ks[row][seg * 8] =
                    *(const uint4*)(Kh + (size_t)(kt0 + row) * D_MOD + h * DH + seg * 8);
                uint4 vv = *(const uint4*)(Vh + (size_t)(kt0 + row) * D_MOD + h * DH + seg * 8);
                uint32_t ox = __shfl_xor_sync(0xFFFFFFFFu, vv.x, 8);
                uint32_t oy = __shfl_xor_sync(0xFFFFFFFFu, vv.y, 8);
                uint32_t oz = __shfl_xor_sync(0xFFFFFFFFu, vv.z, 8);
                uint32_t ow = __shfl_xor_sync(0xFFFFFFFFu, vv.w, 8);
                int prow = row & ~1;
                int dbase = seg * 8 + (odd ? 4 : 0);
                uint32_t a0 = odd ? oz : vv.x;   // even row's halves
                uint32_t a1 = odd ? ow : vv.y;
                uint32_t b0 = odd ? vv.z : ox;   // odd row's halves
                uint32_t b1 = odd ? vv.w : oy;
                *(uint32_t*)&Vts[dbase + 0][prow] = __byte_perm(a0, b0, 0x5410);
                *(uint32_t*)&Vts[dbase + 1][prow] = __byte_perm(a0, b0, 0x7632);
                *(uint32_t*)&Vts[dbase + 2][prow] = __byte_perm(a1, b1, 0x5410);
                *(uint32_t*)&Vts[dbase + 3][prow] = __byte_perm(a1, b1, 0x7632);
            }
        }
        if (tid < 64) mbias[tid] = mask[kt0 + tid] ? 0.f : -1e30f;
        __syncthreads();

        // S = Q K^T
        float sf[8][4];
#pragma unroll
        for (int nt = 0; nt < 8; nt++) {
            sf[nt][0] = sf[nt][1] = sf[nt][2] = sf[nt][3] = 0.f;
#pragma unroll
            for (int kk = 0; kk < 4; kk++) {
                uint32_t bf[2];
                bf[0] = *(const uint32_t*)&Ks[nt * 8 + g][kk * 16 + 2 * qd];
                bf[1] = *(const uint32_t*)&Ks[nt * 8 + g][kk * 16 + 8 + 2 * qd];
                mma_f16(sf[nt], qf[kk], bf);
            }
            int j0 = nt * 8 + 2 * qd;
            float mb0 = mbias[j0], mb1 = mbias[j0 + 1];
            sf[nt][0] += mb0; sf[nt][1] += mb1; sf[nt][2] += mb0; sf[nt][3] += mb1;
            if (t == 0) {
                if (j0     < i_lo) sf[nt][0] = -1e30f;
                if (j0 + 1 < i_lo) sf[nt][1] = -1e30f;
                if (j0     < i_hi) sf[nt][2] = -1e30f;
                if (j0 + 1 < i_hi) sf[nt][3] = -1e30f;
            } else if (t == 8) {
                if (j0     > i_lo) sf[nt][0] = -1e30f;
                if (j0 + 1 > i_lo) sf[nt][1] = -1e30f;
                if (j0     > i_hi) sf[nt][2] = -1e30f;
                if (j0 + 1 > i_hi) sf[nt][3] = -1e30f;
            }
        }

        // online softmax (rows g / g+8; quad lanes share rows)
        float rm0 = -1e30f, rm1 = -1e30f;
#pragma unroll
        for (int nt = 0; nt < 8; nt++) {
            rm0 = fmaxf(rm0, fmaxf(sf[nt][0], sf[nt][1]));
            rm1 = fmaxf(rm1, fmaxf(sf[nt][2], sf[nt][3]));
        }
        rm0 = fmaxf(rm0, __shfl_xor_sync(0xFFFFFFFFu, rm0, 1));
        rm0 = fmaxf(rm0, __shfl_xor_sync(0xFFFFFFFFu, rm0, 2));
        rm1 = fmaxf(rm1, __shfl_xor_sync(0xFFFFFFFFu, rm1, 1));
        rm1 = fmaxf(rm1, __shfl_xor_sync(0xFFFFFFFFu, rm1, 2));
        float nm0 = fmaxf(m0, rm0), nm1 = fmaxf(m1, rm1);
        float sc0 = __expf(m0 - nm0), sc1 = __expf(m1 - nm1);

        uint32_t pf[4][4];
        float rs0 = 0.f, rs1 = 0.f;
#pragma unroll
        for (int nt = 0; nt < 8; nt++) {
            float e0 = __expf(sf[nt][0] - nm0);
            float e1 = __expf(sf[nt][1] - nm0);
            float e2 = __expf(sf[nt][2] - nm1);
            float e3 = __expf(sf[nt][3] - nm1);
            rs0 += e0 + e1; rs1 += e2 + e3;
            __half2 p01 = __floats2half2_rn(e0, e1);
            __half2 p23 = __floats2half2_rn(e2, e3);
            pf[nt >> 1][(nt & 1) * 2 + 0] = *(uint32_t*)&p01;
            pf[nt >> 1][(nt & 1) * 2 + 1] = *(uint32_t*)&p23;
        }
        rs0 += __shfl_xor_sync(0xFFFFFFFFu, rs0, 1);
        rs0 += __shfl_xor_sync(0xFFFFFFFFu, rs0, 2);
        rs1 += __shfl_xor_sync(0xFFFFFFFFu, rs1, 1);
        rs1 += __shfl_xor_sync(0xFFFFFFFFu, rs1, 2);
        l0 = l0 * sc0 + rs0;
        l1 = l1 * sc1 + rs1;
        m0 = nm0; m1 = nm1;
#pragma unroll
        for (int ntd = 0; ntd < 8; ntd++) {
            oacc[ntd][0] *= sc0; oacc[ntd][1] *= sc0;
            oacc[ntd][2] *= sc1; oacc[ntd][3] *= sc1;
        }
        // O += P V
#pragma unroll
        for (int ntd = 0; ntd < 8; ntd++) {
#pragma unroll
            for (int kk = 0; kk < 4; kk++) {
                uint32_t bf[2];
                bf[0] = *(const uint32_t*)&Vts[ntd * 8 + g][kk * 16 + 2 * qd];
                bf[1] = *(const uint32_t*)&Vts[ntd * 8 + g][kk * 16 + 8 + 2 * qd];
                mma_f16(oacc[ntd], pf[kk], bf);
            }
        }
    }

    float inv0 = 1.f / l0, inv1 = 1.f / l1;
    int row0 = qt0 + i_lo;
#pragma unroll
    for (int ntd = 0; ntd < 8; ntd++) {
        int col = h * DH + ntd * 8 + 2 * qd;
        __half2 o0 = __floats2half2_rn(oacc[ntd][0] * inv0, oacc[ntd][1] * inv0);
        __half2 o1 = __floats2half2_rn(oacc[ntd][2] * inv1, oacc[ntd][3] * inv1);
        *(__half2*)(O + (size_t)row0 * D_MOD + col)       = o0;
        *(__half2*)(O + (size_t)(row0 + 8) * D_MOD + col) = o1;
    }
}

// ---------------- pooling + head ----------------
__global__ void zero_pooled_kernel(float* __restrict__ pooled)
{
    for (int d = threadIdx.x; d < D_MOD; d += blockDim.x) pooled[d] = 0.f;
}

__global__ void msum_kernel(const int* __restrict__ mask, float* __restrict__ out)
{
    __shared__ float red[256];
    int tid = threadIdx.x;
    float s = 0.f;
    for (int i = tid; i < S_LEN; i += 256) s += (float)mask[i];
    red[tid] = s; __syncthreads();
    for (int o = 128; o > 0; o >>= 1) { if (tid < o) red[tid] += red[tid + o]; __syncthreads(); }
    if (tid == 0) out[0] = fmaxf(red[0], 1e-9f);
}

__global__ void __launch_bounds__(256) pool_kernel(const float* __restrict__ X,
                                                   const int* __restrict__ mask,
                                                   float* __restrict__ pooled)
{
    int s0 = blockIdx.x * 256;
    int tid = threadIdx.x;
    float a0 = 0.f, a1 = 0.f, a2 = 0.f;
    for (int r = 0; r < 256; r++) {
        float mf = (float)mask[s0 + r];
        const float* xp = X + (size_t)(s0 + r) * D_MOD;
        a0 += xp[tid]       * mf;
        a1 += xp[tid + 256] * mf;
        a2 += xp[tid + 512] * mf;
    }
    atomicAdd(&pooled[tid],       a0);
    atomicAdd(&pooled[tid + 256], a1);
    atomicAdd(&pooled[tid + 512], a2);
}

__global__ void head1_kernel(const float* __restrict__ pooled,
                             const float* __restrict__ W1, const float* __restrict__ b1,
                             const float* __restrict__ msum, float* __restrict__ h1)
{
    int i = threadIdx.x;
    float inv = 1.0f / msum[0];
    float dot = 0.f;
    for (int d = 0; d < D_MOD; d++) dot += pooled[d] * W1[(size_t)d * 512 + i];
    h1[i] = fmaxf(dot * inv + b1[i], 0.f);
}

__global__ void head2_kernel(const float* __restrict__ h1,
                             const float* __restrict__ W2, const float* __restrict__ b2,
                             float* __restrict__ h2)
{
    int i = threadIdx.x;
    if (i < 250) {
        float dot = 0.f;
        for (int d = 0; d < 512; d++) dot += h1[d] * W2[(size_t)d * 250 + i];
        h2[i] = fmaxf(dot + b2[i], 0.f);
    } else if (i < 256) {
        h2[i] = 0.f;
    }
}

__global__ void head3_kernel(const float* __restrict__ h2,
                             const float* __restrict__ W3, const float* __restrict__ b3,
                             float* __restrict__ out, int out_size)
{
    __shared__ float red[256];
    __shared__ float pred;
    int tid = threadIdx.x;
    float v = (tid < 250) ? h2[tid] * W3[tid] : 0.f;
    red[tid] = v; __syncthreads();
    for (int o = 128; o > 0; o >>= 1) { if (tid < o) red[tid] += red[tid + o]; __syncthreads(); }
    if (tid == 0) pred = red[0] + b3[0];
    __syncthreads();
    for (int i = tid; i < out_size; i += 256) out[i] = pred;
}

// ---------------- launch ----------------
extern "C" void kernel_launch(void* const* d_in, const int* in_sizes, int n_in,
                              void* d_out, int out_size)
{
    const int*   ids    = (const int*)  d_in[0];
    const int*   mask   = (const int*)  d_in[1];
    const float* wemb   = (const float*)d_in[2];
    const float* pemb   = (const float*)d_in[3];
    const float* emb_g  = (const float*)d_in[4];
    const float* emb_b  = (const float*)d_in[5];
    const float* Wq     = (const float*)d_in[6];
    const float* Wk     = (const float*)d_in[7];
    const float* Wv     = (const float*)d_in[8];
    const float* Wo     = (const float*)d_in[9];
    const float* bq     = (const float*)d_in[10];
    const float* bk     = (const float*)d_in[11];
    const float* bv     = (const float*)d_in[12];
    const float* bo     = (const float*)d_in[13];
    const float* ln1_g  = (const float*)d_in[14];
    const float* ln1_b  = (const float*)d_in[15];
    const float* Wff1   = (const float*)d_in[16];
    const float* bff1   = (const float*)d_in[17];
    const float* Wff2   = (const float*)d_in[18];
    const float* bff2   = (const float*)d_in[19];
    const float* ln2_g  = (const float*)d_in[20];
    const float* ln2_b  = (const float*)d_in[21];
    const float* W1     = (const float*)d_in[22];
    const float* b1     = (const float*)d_in[23];
    const float* W2     = (const float*)d_in[24];
    const float* b2     = (const float*)d_in[25];
    const float* W3     = (const float*)d_in[26];
    const float* b3     = (const float*)d_in[27];
    float* out = (float*)d_out;

    float *x, *o, *pooled, *h1, *h2, *msum, *bqkv;
    __half *xr, *qkvh, *a, *ff, *qkvT, *WoT, *f1T, *f2T;
    cudaGetSymbolAddress((void**)&x,      g_x);
    cudaGetSymbolAddress((void**)&xr,     g_xr);
    cudaGetSymbolAddress((void**)&qkvh,   g_qkvh);
    cudaGetSymbolAddress((void**)&a,      g_a);
    cudaGetSymbolAddress((void**)&o,      g_o);
    cudaGetSymbolAddress((void**)&ff,     g_ff);
    cudaGetSymbolAddress((void**)&pooled, g_pooled);
    cudaGetSymbolAddress((void**)&h1,     g_h1);
    cudaGetSymbolAddress((void**)&h2,     g_h2);
    cudaGetSymbolAddress((void**)&msum,   g_msum);
    cudaGetSymbolAddress((void**)&qkvT,   g_qkvT);
    cudaGetSymbolAddress((void**)&WoT,    g_WoT);
    cudaGetSymbolAddress((void**)&f1T,    g_f1T);
    cudaGetSymbolAddress((void**)&f2T,    g_f2T);
    cudaGetSymbolAddress((void**)&bqkv,   g_bqkv);

    cudaFuncSetAttribute(tgemm_kernel, cudaFuncAttributeMaxDynamicSharedMemorySize, TGH_SMEM_BYTES);

    dim3 tgQKV(3 * D_MOD / 128, S_LEN / 128);   // (18, 32)
    dim3 tg768 (D_MOD / 128, S_LEN / 128);      // (6, 32)
    dim3 tg3072(FF_DIM / 128, S_LEN / 128);     // (24, 32)

    prep_kernel<<<27652, dim3(32, 8)>>>(Wq, Wk, Wv, Wo, Wff1, Wff2, bq, bk, bv,
                                        qkvT, WoT, f1T, f2T, bqkv);
    embed_kernel<<<S_LEN, 256>>>(ids, wemb, pemb, x);
    ln_kernel<<<S_LEN, 256>>>(x, nullptr, emb_g, emb_b, xr);

    for (int l = 0; l < N_LAYER; l++) {
        const __half* qkvT_l = qkvT + (size_t)l * 3 * D_MOD * D_MOD;
        const __half* WoT_l  = WoT  + (size_t)l * D_MOD * D_MOD;
        const __half* f1T_l  = f1T  + (size_t)l * D_MOD * FF_DIM;
        const __half* f2T_l  = f2T  + (size_t)l * FF_DIM * D_MOD;
        const float*  bqkv_l = bqkv + (size_t)l * 3 * D_MOD;

        tgemm_kernel<<<tgQKV, 256, TGH_SMEM_BYTES>>>(xr, qkvT_l, bqkv_l, qkvh,
                                                     S_LEN, 3 * D_MOD, D_MOD, 3);
        fattn_kernel<<<dim3(S_LEN / 64, N_HEAD), 128>>>(qkvh, mask, a);
        tgemm_kernel<<<tg768, 256, TGH_SMEM_BYTES>>>(a, WoT_l, bo + l * D_MOD, o,
                                                     S_LEN, D_MOD, D_MOD, 0);
        ln_kernel<<<S_LEN, 256>>>(x, o, ln1_g + l * D_MOD, ln1_b + l * D_MOD, xr);

        tgemm_kernel<<<tg3072, 256, TGH_SMEM_BYTES>>>(xr, f1T_l, bff1 + l * FF_DIM, ff,
                                                      S_LEN, FF_DIM, D_MOD, 2);
        tgemm_kernel<<<tg768, 256, TGH_SMEM_BYTES>>>(ff, f2T_l, bff2 + l * D_MOD, o,
                                                     S_LEN, D_MOD, FF_DIM, 0);
        ln_kernel<<<S_LEN, 256>>>(x, o, ln2_g + l * D_MOD, ln2_b + l * D_MOD, xr);
    }

    zero_pooled_kernel<<<1, 256>>>(pooled);
    msum_kernel<<<1, 256>>>(mask, msum);
    pool_kernel<<<S_LEN / 256, 256>>>(x, mask, pooled);
    head1_kernel<<<1, 512>>>(pooled, W1, b1, msum, h1);
    head2_kernel<<<1, 256>>>(h1, W2, b2, h2);
    head3_kernel<<<1, 256>>>(h2, W3, b3, out, out_size);
}

// round 15
// speedup vs baseline: 8.2193x; 1.0603x over previous
#include <cuda_runtime.h>
#include <cuda_fp16.h>
#include <math.h>
#include <stdint.h>

#define S_LEN 4096
#define D_MOD 768
#define N_HEAD 12
#define DH 64
#define N_LAYER 4
#define FF_DIM 3072
#define WIN 256

// ---------------- scratch (device globals; no allocation) ----------------
__device__ float  g_x  [S_LEN * D_MOD];
__device__ __half g_xr [S_LEN * D_MOD];
__device__ __half g_qkvh[3 * S_LEN * D_MOD];     // q|k|v fp16, sectioned [sec][S][768]
__device__ __half g_a  [S_LEN * D_MOD];
__device__ float  g_o  [S_LEN * D_MOD];
__device__ __half g_ff [S_LEN * FF_DIM];
__device__ float  g_pooled[D_MOD];
__device__ float  g_h1[512];
__device__ float  g_h2[256];
__device__ float  g_msum[1];
__device__ __half g_qkvT[N_LAYER * 3 * D_MOD * D_MOD];
__device__ __half g_WoT [N_LAYER * D_MOD * D_MOD];
__device__ __half g_f1T [N_LAYER * D_MOD * FF_DIM];
__device__ __half g_f2T [N_LAYER * FF_DIM * D_MOD];
__device__ float  g_bqkv[N_LAYER * 3 * D_MOD];

__device__ __forceinline__ void mma_f16(float* d, const uint32_t* a, const uint32_t* b) {
    asm volatile(
        "mma.sync.aligned.m16n8k16.row.col.f32.f16.f16.f32 "
        "{%0,%1,%2,%3}, {%4,%5,%6,%7}, {%8,%9}, {%0,%1,%2,%3};\n"
        : "+f"(d[0]), "+f"(d[1]), "+f"(d[2]), "+f"(d[3])
        : "r"(a[0]), "r"(a[1]), "r"(a[2]), "r"(a[3]), "r"(b[0]), "r"(b[1]));
}

#define LDSM_X4(d0, d1, d2, d3, addr) \
    asm volatile("ldmatrix.sync.aligned.m8n8.x4.shared.b16 {%0,%1,%2,%3}, [%4];" \
        : "=r"(d0), "=r"(d1), "=r"(d2), "=r"(d3) : "r"(addr))

__device__ __forceinline__ uint32_t smem_u32(const void* p) {
    uint32_t a;
    asm("{ .reg .u64 t; cvta.to.shared.u64 t, %1; cvt.u32.u64 %0, t; }" : "=r"(a) : "l"(p));
    return a;
}

__device__ __forceinline__ void cp_async16(uint32_t saddr, const void* g) {
    asm volatile("cp.async.cg.shared.global [%0], [%1], 16;" :: "r"(saddr), "l"(g) : "memory");
}
#define CP_COMMIT() asm volatile("cp.async.commit_group;" ::: "memory")
#define CP_WAIT1()  asm volatile("cp.async.wait_group 1;" ::: "memory")
#define CP_WAIT0()  asm volatile("cp.async.wait_group 0;" ::: "memory")

// ---------------- unified weight prep: transpose + fp16 + bias fuse --------
__global__ void prep_kernel(const float* __restrict__ Wq, const float* __restrict__ Wk,
                            const float* __restrict__ Wv, const float* __restrict__ Wo,
                            const float* __restrict__ Wff1, const float* __restrict__ Wff2,
                            const float* __restrict__ bq, const float* __restrict__ bk,
                            const float* __restrict__ bv,
                            __half* __restrict__ qkvT, __half* __restrict__ WoT,
                            __half* __restrict__ f1T, __half* __restrict__ f2T,
                            float* __restrict__ bqkv)
{
    int t = blockIdx.x;
    int tx = threadIdx.x, ty = threadIdx.y;
    if (t >= 27648) {
        int layer = t - 27648;
        int flat = ty * 32 + tx;
        for (int i = flat; i < D_MOD; i += 256) {
            bqkv[layer * 3 * D_MOD + i]             = bq[layer * D_MOD + i];
            bqkv[layer * 3 * D_MOD + D_MOD + i]     = bk[layer * D_MOD + i];
            bqkv[layer * 3 * D_MOD + 2 * D_MOD + i] = bv[layer * D_MOD + i];
        }
        return;
    }
    const float* src; __half* dst; int K, N, k0, n0;
    if (t < 6912) {
        int part = t / 2304, r = t % 2304;
        int layer = r / 576, tile = r % 576;
        K = 768; N = 768;
        src = (part == 0 ? Wq : (part == 1 ? Wk : Wv)) + (size_t)layer * 768 * 768;
        dst = qkvT + (size_t)layer * 3 * 768 * 768 + (size_t)part * 768 * 768;
        k0 = (tile / 24) * 32; n0 = (tile % 24) * 32;
    } else if (t < 9216) {
        int r = t - 6912, layer = r / 576, tile = r % 576;
        K = 768; N = 768;
        src = Wo + (size_t)layer * 768 * 768;
        dst = WoT + (size_t)layer * 768 * 768;
        k0 = (tile / 24) * 32; n0 = (tile % 24) * 32;
    } else if (t < 18432) {
        int r = t - 9216, layer = r / 2304, tile = r % 2304;
        K = 768; N = 3072;
        src = Wff1 + (size_t)layer * 768 * 3072;
        dst = f1T + (size_t)layer * 768 * 3072;
        k0 = (tile / 96) * 32; n0 = (tile % 96) * 32;
    } else {
        int r = t - 18432, layer = r / 2304, tile = r % 2304;
        K = 3072; N = 768;
        src = Wff2 + (size_t)layer * 3072 * 768;
        dst = f2T + (size_t)layer * 3072 * 768;
        k0 = (tile / 24) * 32; n0 = (tile % 24) * 32;
    }
    __shared__ float tl[32][33];
#pragma unroll
    for (int i = 0; i < 32; i += 8)
        tl[ty + i][tx] = src[(size_t)(k0 + ty + i) * N + n0 + tx];
    __syncthreads();
#pragma unroll
    for (int i = 0; i < 32; i += 8)
        dst[(size_t)(n0 + ty + i) * K + k0 + tx] = __float2half_rn(tl[tx][ty + i]);
}

// ---------------- fp16 mma.sync GEMM, cp.async 3-stage, ldmatrix frags -----
#define PAD_H 72
#define TGH_TILE (128 * PAD_H)
#define TGH_STAGES 3
#define TGH_SMEM_BYTES (TGH_STAGES * 2 * TGH_TILE * 2)

__device__ __forceinline__ void tg_copy_h(const __half* __restrict__ Ab,
                                          const __half* __restrict__ Bb,
                                          int K, int k0,
                                          __half* sA, __half* sB, int tid)
{
#pragma unroll
    for (int i = 0; i < 4; i++) {
        int idx = tid + i * 256;
        int row = idx >> 3, seg = idx & 7;
        uint32_t da = (uint32_t)__cvta_generic_to_shared(sA + row * PAD_H + seg * 8);
        uint32_t db = (uint32_t)__cvta_generic_to_shared(sB + row * PAD_H + seg * 8);
        cp_async16(da, Ab + (size_t)row * K + k0 + seg * 8);
        cp_async16(db, Bb + (size_t)row * K + k0 + seg * 8);
    }
}

__global__ void __launch_bounds__(256, 2) tgemm_kernel(const __half* __restrict__ A,
                                                       const __half* __restrict__ Bt,
                                                       const float* __restrict__ bias,
                                                       void* __restrict__ Cout,
                                                       int M, int N, int K, int epi)
{
    extern __shared__ __half smh[];
    __half* sA = smh;
    __half* sB = smh + TGH_STAGES * TGH_TILE;

    const int tid  = threadIdx.x;
    const int wid  = tid >> 5;
    const int lane = tid & 31;
    const int wm   = wid & 1;
    const int wn   = wid >> 1;
    const int g    = lane >> 2;
    const int cq2  = (lane & 3) * 2;
    const int m0 = blockIdx.y * 128;
    const int n0 = blockIdx.x * 128;
    const int NC = K >> 6;

    const __half* Ab = A  + (size_t)m0 * K;
    const __half* Bb = Bt + (size_t)n0 * K;

    // ldmatrix lane offsets (bytes), pitch 72 halves = 144B: conflict-free
    const uint32_t smbase = smem_u32(smh);
    const uint32_t a_off = ((wm * 64 + (lane & 7) + ((lane >> 3) & 1) * 8) * PAD_H
                            + (lane >> 4) * 8) * 2;
    const uint32_t b_off = ((wn * 32 + (lane & 7) + (lane >> 4) * 8) * PAD_H
                            + ((lane >> 3) & 1) * 8) * 2;

    float acc[4][4][4];
#pragma unroll
    for (int i = 0; i < 4; i++)
#pragma unroll
        for (int j = 0; j < 4; j++)
#pragma unroll
            for (int r = 0; r < 4; r++) acc[i][j][r] = 0.f;

    tg_copy_h(Ab, Bb, K, 0,  sA,            sB,            tid); CP_COMMIT();
    tg_copy_h(Ab, Bb, K, 64, sA + TGH_TILE, sB + TGH_TILE, tid); CP_COMMIT();

    int st = 0;
    for (int c = 0; c < NC; c++) {
        if (c + 1 < NC) { CP_WAIT1(); } else { CP_WAIT0(); }
        __syncthreads();
        if (c + 2 < NC) {
            int ns = st + 2; if (ns >= TGH_STAGES) ns -= TGH_STAGES;
            tg_copy_h(Ab, Bb, K, (c + 2) << 6, sA + ns * TGH_TILE, sB + ns * TGH_TILE, tid);
            CP_COMMIT();
        }
        const uint32_t aBase = smbase + st * (TGH_TILE * 2) + a_off;
        const uint32_t bBase = smbase + (TGH_STAGES + st) * (TGH_TILE * 2) + b_off;
#pragma unroll
        for (int kk = 0; kk < 4; kk++) {
            uint32_t af[4][4], bf[4][2];
#pragma unroll
            for (int mt = 0; mt < 4; mt++)
                LDSM_X4(af[mt][0], af[mt][1], af[mt][2], af[mt][3],
                        aBase + (mt * 16 * PAD_H + kk * 16) * 2);
#pragma unroll
            for (int ntp = 0; ntp < 2; ntp++)
                LDSM_X4(bf[2 * ntp][0], bf[2 * ntp][1], bf[2 * ntp + 1][0], bf[2 * ntp + 1][1],
                        bBase + (ntp * 16 * PAD_H + kk * 16) * 2);
#pragma unroll
            for (int mt = 0; mt < 4; mt++)
#pragma unroll
                for (int nt = 0; nt < 4; nt++)
                    mma_f16(acc[mt][nt], af[mt], bf[nt]);
        }
        st++; if (st >= TGH_STAGES) st = 0;
    }

    // ---- epilogue
    const int sec = (epi == 3) ? (n0 / 768) : 0;
    const bool qsc = (epi == 3) && (sec == 0);
    __half* dsec = (__half*)Cout + (size_t)sec * S_LEN * 768;
    const int nb = n0 - sec * 768;
    float* Cf = (float*)Cout;
    __half* Ch = (__half*)Cout;
#pragma unroll
    for (int mt = 0; mt < 4; mt++) {
        int row = m0 + wm * 64 + mt * 16 + g;
#pragma unroll
        for (int nt = 0; nt < 4; nt++) {
            int colw = wn * 32 + nt * 8 + cq2;
            int col = n0 + colw;
            float bb0 = bias[col], bb1 = bias[col + 1];
            float v0 = acc[mt][nt][0] + bb0;
            float v1 = acc[mt][nt][1] + bb1;
            float v2 = acc[mt][nt][2] + bb0;
            float v3 = acc[mt][nt][3] + bb1;
            if (epi == 3) {
                if (qsc) { v0 *= 0.125f; v1 *= 0.125f; v2 *= 0.125f; v3 *= 0.125f; }
                int lcol = nb + colw;
                *(__half2*)(dsec + (size_t)row * 768 + lcol)       = __floats2half2_rn(v0, v1);
                *(__half2*)(dsec + (size_t)(row + 8) * 768 + lcol) = __floats2half2_rn(v2, v3);
            } else if (epi == 2) {
                v0 = 0.5f * v0 * (1.0f + erff(v0 * 0.70710678118654752f));
                v1 = 0.5f * v1 * (1.0f + erff(v1 * 0.70710678118654752f));
                v2 = 0.5f * v2 * (1.0f + erff(v2 * 0.70710678118654752f));
                v3 = 0.5f * v3 * (1.0f + erff(v3 * 0.70710678118654752f));
                *(__half2*)(Ch + (size_t)row * N + col)       = __floats2half2_rn(v0, v1);
                *(__half2*)(Ch + (size_t)(row + 8) * N + col) = __floats2half2_rn(v2, v3);
            } else {
                *(float2*)(Cf + (size_t)row * N + col)       = make_float2(v0, v1);
                *(float2*)(Cf + (size_t)(row + 8) * N + col) = make_float2(v2, v3);
            }
        }
    }
}

// ---------------- embedding ----------------
__global__ void embed_kernel(const int* __restrict__ ids,
                             const float* __restrict__ wemb,
                             const float* __restrict__ pemb,
                             float* __restrict__ X)
{
    int row = blockIdx.x;
    int id  = ids[row];
    const float* wp = wemb + (size_t)id * D_MOD;
    const float* pp = pemb + (size_t)row * D_MOD;
    float* xp = X + (size_t)row * D_MOD;
    for (int d = threadIdx.x; d < D_MOD; d += blockDim.x)
        xp[d] = wp[d] + pp[d];
}

// -------- LayerNorm (optional residual), in-place on X; fp16 copy to XR ----
__global__ void __launch_bounds__(256) ln_kernel(float* __restrict__ X,
                                                 const float* __restrict__ Aadd,
                                                 const float* __restrict__ g,
                                                 const float* __restrict__ b,
                                                 __half* __restrict__ XR)
{
    int row = blockIdx.x;
    int tid = threadIdx.x;
    int lane = tid & 31, wid = tid >> 5;
    __shared__ float red[8];
    float vals[3];
    float s = 0.f;
    const size_t base = (size_t)row * D_MOD;
#pragma unroll
    for (int i = 0; i < 3; i++) {
        int d = tid + i * 256;
        float v = X[base + d];
        if (Aadd) v += Aadd[base + d];
        vals[i] = v;
        s += v;
    }
#pragma unroll
    for (int o = 16; o > 0; o >>= 1) s += __shfl_xor_sync(0xFFFFFFFFu, s, o);
    if (lane == 0) red[wid] = s;
    __syncthreads();
    float tot = red[0] + red[1] + red[2] + red[3] + red[4] + red[5] + red[6] + red[7];
    float mean = tot * (1.0f / D_MOD);
    float ss = 0.f;
#pragma unroll
    for (int i = 0; i < 3; i++) { float dv = vals[i] - mean; ss += dv * dv; }
#pragma unroll
    for (int o = 16; o > 0; o >>= 1) ss += __shfl_xor_sync(0xFFFFFFFFu, ss, o);
    __syncthreads();
    if (lane == 0) red[wid] = ss;
    __syncthreads();
    float tot2 = red[0] + red[1] + red[2] + red[3] + red[4] + red[5] + red[6] + red[7];
    float rstd = rsqrtf(tot2 * (1.0f / D_MOD) + 1e-5f);
#pragma unroll
    for (int i = 0; i < 3; i++) {
        int d = tid + i * 256;
        float outv = (vals[i] - mean) * rstd * g[d] + b[d];
        X[base + d] = outv;
        XR[base + d] = __float2half_rn(outv);
    }
}

// ---------------- tensor-core band flash attention --------------------------
#define APITCH 72
#define VPITCH 74
__global__ void __launch_bounds__(128) fattn_kernel(const __half* __restrict__ QKVh,
                                                    const int* __restrict__ mask,
                                                    __half* __restrict__ O)
{
    const __half* Qh = QKVh;
    const __half* Kh = QKVh + (size_t)S_LEN * D_MOD;
    const __half* Vh = QKVh + 2 * (size_t)S_LEN * D_MOD;

    const int qb = blockIdx.x;
    const int h  = blockIdx.y;
    const int qt0 = qb * 64;
    const int tid = threadIdx.x;
    const int w = tid >> 5, lane = tid & 31;
    const int g = lane >> 2, qd = lane & 3;

    __shared__ __align__(16) __half Qs[64][APITCH];
    __shared__ __align__(16) __half Ks[64][APITCH];
    __shared__ __align__(16) __half Vts[64][VPITCH];   // [d][key]
    __shared__ float mbias[64];

    // stage Q
    {
        int r = tid >> 3, seg = tid & 7;
#pragma unroll
        for (int p = 0; p < 4; p++) {
            int row = p * 16 + r;
            *(uint4*)&Qs[row][seg * 8] =
                *(const uint4*)(Qh + (size_t)(qt0 + row) * D_MOD + h * DH + seg * 8);
        }
    }
    __syncthreads();

    uint32_t qf[4][4];
    {
        int r0 = w * 16 + g;
#pragma unroll
        for (int kk = 0; kk < 4; kk++) {
            qf[kk][0] = *(const uint32_t*)&Qs[r0][kk * 16 + 2 * qd];
            qf[kk][1] = *(const uint32_t*)&Qs[r0 + 8][kk * 16 + 2 * qd];
            qf[kk][2] = *(const uint32_t*)&Qs[r0][kk * 16 + 8 + 2 * qd];
            qf[kk][3] = *(const uint32_t*)&Qs[r0 + 8][kk * 16 + 8 + 2 * qd];
        }
    }

    // ldmatrix lane offset for Ks B-fragments (pitch 72: conflict-free)
    const uint32_t ks_base = smem_u32(Ks) +
        (((lane & 7) + (lane >> 4) * 8) * APITCH + ((lane >> 3) & 1) * 8) * 2;

    float oacc[8][4];
#pragma unroll
    for (int i = 0; i < 8; i++)
#pragma unroll
        for (int r = 0; r < 4; r++) oacc[i][r] = 0.f;
    float m0 = -1e30f, m1 = -1e30f, l0 = 0.f, l1 = 0.f;
    const int i_lo = w * 16 + g, i_hi = i_lo + 8;

    for (int t = 0; t < 9; t++) {
        const int kt0 = qt0 + (t - 4) * 64;
        if (kt0 < 0 || kt0 >= S_LEN) continue;
        __syncthreads();
        {
            int r = tid >> 3, seg = tid & 7;
            bool odd = (r & 1) != 0;
#pragma unroll
            for (int p = 0; p < 4; p++) {
                int row = p * 16 + r;
                *(uint4*)&Ks[row][seg * 8] =
                    *(const uint4*)(Kh + (size_t)(kt0 + row) * D_MOD + h * DH + seg * 8);
                uint4 vv = *(const uint4*)(Vh + (size_t)(kt0 + row) * D_MOD + h * DH + seg * 8);
                uint32_t ox = __shfl_xor_sync(0xFFFFFFFFu, vv.x, 8);
                uint32_t oy = __shfl_xor_sync(0xFFFFFFFFu, vv.y, 8);
                uint32_t oz = __shfl_xor_sync(0xFFFFFFFFu, vv.z, 8);
                uint32_t ow = __shfl_xor_sync(0xFFFFFFFFu, vv.w, 8);
                int prow = row & ~1;
                int dbase = seg * 8 + (odd ? 4 : 0);
                uint32_t a0 = odd ? oz : vv.x;
                uint32_t a1 = odd ? ow : vv.y;
                uint32_t b0 = odd ? vv.z : ox;
                uint32_t b1 = odd ? vv.w : oy;
                *(uint32_t*)&Vts[dbase + 0][prow] = __byte_perm(a0, b0, 0x5410);
                *(uint32_t*)&Vts[dbase + 1][prow] = __byte_perm(a0, b0, 0x7632);
                *(uint32_t*)&Vts[dbase + 2][prow] = __byte_perm(a1, b1, 0x5410);
                *(uint32_t*)&Vts[dbase + 3][prow] = __byte_perm(a1, b1, 0x7632);
            }
        }
        if (tid < 64) mbias[tid] = mask[kt0 + tid] ? 0.f : -1e30f;
        __syncthreads();

        // S = Q K^T via ldmatrix B-frags
        float sf[8][4];
#pragma unroll
        for (int nt = 0; nt < 8; nt++)
            sf[nt][0] = sf[nt][1] = sf[nt][2] = sf[nt][3] = 0.f;
#pragma unroll
        for (int kk = 0; kk < 4; kk++) {
            uint32_t kf[8][2];
#pragma unroll
            for (int ntp = 0; ntp < 4; ntp++)
                LDSM_X4(kf[2 * ntp][0], kf[2 * ntp][1], kf[2 * ntp + 1][0], kf[2 * ntp + 1][1],
                        ks_base + (ntp * 16 * APITCH + kk * 16) * 2);
#pragma unroll
            for (int nt = 0; nt < 8; nt++)
                mma_f16(sf[nt], qf[kk], kf[nt]);
        }
#pragma unroll
        for (int nt = 0; nt < 8; nt++) {
            int j0 = nt * 8 + 2 * qd;
            float mb0 = mbias[j0], mb1 = mbias[j0 + 1];
            sf[nt][0] += mb0; sf[nt][1] += mb1; sf[nt][2] += mb0; sf[nt][3] += mb1;
            if (t == 0) {
                if (j0     < i_lo) sf[nt][0] = -1e30f;
                if (j0 + 1 < i_lo) sf[nt][1] = -1e30f;
                if (j0     < i_hi) sf[nt][2] = -1e30f;
                if (j0 + 1 < i_hi) sf[nt][3] = -1e30f;
            } else if (t == 8) {
                if (j0     > i_lo) sf[nt][0] = -1e30f;
                if (j0 + 1 > i_lo) sf[nt][1] = -1e30f;
                if (j0     > i_hi) sf[nt][2] = -1e30f;
                if (j0 + 1 > i_hi) sf[nt][3] = -1e30f;
            }
        }

        // online softmax
        float rm0 = -1e30f, rm1 = -1e30f;
#pragma unroll
        for (int nt = 0; nt < 8; nt++) {
            rm0 = fmaxf(rm0, fmaxf(sf[nt][0], sf[nt][1]));
            rm1 = fmaxf(rm1, fmaxf(sf[nt][2], sf[nt][3]));
        }
        rm0 = fmaxf(rm0, __shfl_xor_sync(0xFFFFFFFFu, rm0, 1));
        rm0 = fmaxf(rm0, __shfl_xor_sync(0xFFFFFFFFu, rm0, 2));
        rm1 = fmaxf(rm1, __shfl_xor_sync(0xFFFFFFFFu, rm1, 1));
        rm1 = fmaxf(rm1, __shfl_xor_sync(0xFFFFFFFFu, rm1, 2));
        float nm0 = fmaxf(m0, rm0), nm1 = fmaxf(m1, rm1);
        float sc0 = __expf(m0 - nm0), sc1 = __expf(m1 - nm1);

        uint32_t pf[4][4];
        float rs0 = 0.f, rs1 = 0.f;
#pragma unroll
        for (int nt = 0; nt < 8; nt++) {
            float e0 = __expf(sf[nt][0] - nm0);
            float e1 = __expf(sf[nt][1] - nm0);
            float e2 = __expf(sf[nt][2] - nm1);
            float e3 = __expf(sf[nt][3] - nm1);
            rs0 += e0 + e1; rs1 += e2 + e3;
            __half2 p01 = __floats2half2_rn(e0, e1);
            __half2 p23 = __floats2half2_rn(e2, e3);
            pf[nt >> 1][(nt & 1) * 2 + 0] = *(uint32_t*)&p01;
            pf[nt >> 1][(nt & 1) * 2 + 1] = *(uint32_t*)&p23;
        }
        rs0 += __shfl_xor_sync(0xFFFFFFFFu, rs0, 1);
        rs0 += __shfl_xor_sync(0xFFFFFFFFu, rs0, 2);
        rs1 += __shfl_xor_sync(0xFFFFFFFFu, rs1, 1);
        rs1 += __shfl_xor_sync(0xFFFFFFFFu, rs1, 2);
        l0 = l0 * sc0 + rs0;
        l1 = l1 * sc1 + rs1;
        m0 = nm0; m1 = nm1;
#pragma unroll
        for (int ntd = 0; ntd < 8; ntd++) {
            oacc[ntd][0] *= sc0; oacc[ntd][1] *= sc0;
            oacc[ntd][2] *= sc1; oacc[ntd][3] *= sc1;
        }
        // O += P V
#pragma unroll
        for (int ntd = 0; ntd < 8; ntd++) {
#pragma unroll
            for (int kk = 0; kk < 4; kk++) {
                uint32_t bf[2];
                bf[0] = *(const uint32_t*)&Vts[ntd * 8 + g][kk * 16 + 2 * qd];
                bf[1] = *(const uint32_t*)&Vts[ntd * 8 + g][kk * 16 + 8 + 2 * qd];
                mma_f16(oacc[ntd], pf[kk], bf);
            }
        }
    }

    float inv0 = 1.f / l0, inv1 = 1.f / l1;
    int row0 = qt0 + i_lo;
#pragma unroll
    for (int ntd = 0; ntd < 8; ntd++) {
        int col = h * DH + ntd * 8 + 2 * qd;
        __half2 o0 = __floats2half2_rn(oacc[ntd][0] * inv0, oacc[ntd][1] * inv0);
        __half2 o1 = __floats2half2_rn(oacc[ntd][2] * inv1, oacc[ntd][3] * inv1);
        *(__half2*)(O + (size_t)row0 * D_MOD + col)       = o0;
        *(__half2*)(O + (size_t)(row0 + 8) * D_MOD + col) = o1;
    }
}

// ---------------- pooling + head ----------------
__global__ void zero_pooled_kernel(float* __restrict__ pooled)
{
    for (int d = threadIdx.x; d < D_MOD; d += blockDim.x) pooled[d] = 0.f;
}

__global__ void msum_kernel(const int* __restrict__ mask, float* __restrict__ out)
{
    __shared__ float red[256];
    int tid = threadIdx.x;
    float s = 0.f;
    for (int i = tid; i < S_LEN; i += 256) s += (float)mask[i];
    red[tid] = s; __syncthreads();
    for (int o = 128; o > 0; o >>= 1) { if (tid < o) red[tid] += red[tid + o]; __syncthreads(); }
    if (tid == 0) out[0] = fmaxf(red[0], 1e-9f);
}

__global__ void __launch_bounds__(256) pool_kernel(const float* __restrict__ X,
                                                   const int* __restrict__ mask,
                                                   float* __restrict__ pooled)
{
    int s0 = blockIdx.x * 256;
    int tid = threadIdx.x;
    float a0 = 0.f, a1 = 0.f, a2 = 0.f;
    for (int r = 0; r < 256; r++) {
        float mf = (float)mask[s0 + r];
        const float* xp = X + (size_t)(s0 + r) * D_MOD;
        a0 += xp[tid]       * mf;
        a1 += xp[tid + 256] * mf;
        a2 += xp[tid + 512] * mf;
    }
    atomicAdd(&pooled[tid],       a0);
    atomicAdd(&pooled[tid + 256], a1);
    atomicAdd(&pooled[tid + 512], a2);
}

__global__ void head1_kernel(const float* __restrict__ pooled,
                             const float* __restrict__ W1, const float* __restrict__ b1,
                             const float* __restrict__ msum, float* __restrict__ h1)
{
    int i = threadIdx.x;
    float inv = 1.0f / msum[0];
    float dot = 0.f;
    for (int d = 0; d < D_MOD; d++) dot += pooled[d] * W1[(size_t)d * 512 + i];
    h1[i] = fmaxf(dot * inv + b1[i], 0.f);
}

__global__ void head2_kernel(const float* __restrict__ h1,
                             const float* __restrict__ W2, const float* __restrict__ b2,
                             float* __restrict__ h2)
{
    int i = threadIdx.x;
    if (i < 250) {
        float dot = 0.f;
        for (int d = 0; d < 512; d++) dot += h1[d] * W2[(size_t)d * 250 + i];
        h2[i] = fmaxf(dot + b2[i], 0.f);
    } else if (i < 256) {
        h2[i] = 0.f;
    }
}

__global__ void head3_kernel(const float* __restrict__ h2,
                             const float* __restrict__ W3, const float* __restrict__ b3,
                             float* __restrict__ out, int out_size)
{
    __shared__ float red[256];
    __shared__ float pred;
    int tid = threadIdx.x;
    float v = (tid < 250) ? h2[tid] * W3[tid] : 0.f;
    red[tid] = v; __syncthreads();
    for (int o = 128; o > 0; o >>= 1) { if (tid < o) red[tid] += red[tid + o]; __syncthreads(); }
    if (tid == 0) pred = red[0] + b3[0];
    __syncthreads();
    for (int i = tid; i < out_size; i += 256) out[i] = pred;
}

// ---------------- launch ----------------
extern "C" void kernel_launch(void* const* d_in, const int* in_sizes, int n_in,
                              void* d_out, int out_size)
{
    const int*   ids    = (const int*)  d_in[0];
    const int*   mask   = (const int*)  d_in[1];
    const float* wemb   = (const float*)d_in[2];
    const float* pemb   = (const float*)d_in[3];
    const float* emb_g  = (const float*)d_in[4];
    const float* emb_b  = (const float*)d_in[5];
    const float* Wq     = (const float*)d_in[6];
    const float* Wk     = (const float*)d_in[7];
    const float* Wv     = (const float*)d_in[8];
    const float* Wo     = (const float*)d_in[9];
    const float* bq     = (const float*)d_in[10];
    const float* bk     = (const float*)d_in[11];
    const float* bv     = (const float*)d_in[12];
    const float* bo     = (const float*)d_in[13];
    const float* ln1_g  = (const float*)d_in[14];
    const float* ln1_b  = (const float*)d_in[15];
    const float* Wff1   = (const float*)d_in[16];
    const float* bff1   = (const float*)d_in[17];
    const float* Wff2   = (const float*)d_in[18];
    const float* bff2   = (const float*)d_in[19];
    const float* ln2_g  = (const float*)d_in[20];
    const float* ln2_b  = (const float*)d_in[21];
    const float* W1     = (const float*)d_in[22];
    const float* b1     = (const float*)d_in[23];
    const float* W2     = (const float*)d_in[24];
    const float* b2     = (const float*)d_in[25];
    const float* W3     = (const float*)d_in[26];
    const float* b3     = (const float*)d_in[27];
    float* out = (float*)d_out;

    float *x, *o, *pooled, *h1, *h2, *msum, *bqkv;
    __half *xr, *qkvh, *a, *ff, *qkvT, *WoT, *f1T, *f2T;
    cudaGetSymbolAddress((void**)&x,      g_x);
    cudaGetSymbolAddress((void**)&xr,     g_xr);
    cudaGetSymbolAddress((void**)&qkvh,   g_qkvh);
    cudaGetSymbolAddress((void**)&a,      g_a);
    cudaGetSymbolAddress((void**)&o,      g_o);
    cudaGetSymbolAddress((void**)&ff,     g_ff);
    cudaGetSymbolAddress((void**)&pooled, g_pooled);
    cudaGetSymbolAddress((void**)&h1,     g_h1);
    cudaGetSymbolAddress((void**)&h2,     g_h2);
    cudaGetSymbolAddress((void**)&msum,   g_msum);
    cudaGetSymbolAddress((void**)&qkvT,   g_qkvT);
    cudaGetSymbolAddress((void**)&WoT,    g_WoT);
    cudaGetSymbolAddress((void**)&f1T,    g_f1T);
    cudaGetSymbolAddress((void**)&f2T,    g_f2T);
    cudaGetSymbolAddress((void**)&bqkv,   g_bqkv);

    cudaFuncSetAttribute(tgemm_kernel, cudaFuncAttributeMaxDynamicSharedMemorySize, TGH_SMEM_BYTES);

    dim3 tgQKV(3 * D_MOD / 128, S_LEN / 128);   // (18, 32)
    dim3 tg768 (D_MOD / 128, S_LEN / 128);      // (6, 32)
    dim3 tg3072(FF_DIM / 128, S_LEN / 128);     // (24, 32)

    prep_kernel<<<27652, dim3(32, 8)>>>(Wq, Wk, Wv, Wo, Wff1, Wff2, bq, bk, bv,
                                        qkvT, WoT, f1T, f2T, bqkv);
    embed_kernel<<<S_LEN, 256>>>(ids, wemb, pemb, x);
    ln_kernel<<<S_LEN, 256>>>(x, nullptr, emb_g, emb_b, xr);

    for (int l = 0; l < N_LAYER; l++) {
        const __half* qkvT_l = qkvT + (size_t)l * 3 * D_MOD * D_MOD;
        const __half* WoT_l  = WoT  + (size_t)l * D_MOD * D_MOD;
        const __half* f1T_l  = f1T  + (size_t)l * D_MOD * FF_DIM;
        const __half* f2T_l  = f2T  + (size_t)l * FF_DIM * D_MOD;
        const float*  bqkv_l = bqkv + (size_t)l * 3 * D_MOD;

        tgemm_kernel<<<tgQKV, 256, TGH_SMEM_BYTES>>>(xr, qkvT_l, bqkv_l, qkvh,
                                                     S_LEN, 3 * D_MOD, D_MOD, 3);
        fattn_kernel<<<dim3(S_LEN / 64, N_HEAD), 128>>>(qkvh, mask, a);
        tgemm_kernel<<<tg768, 256, TGH_SMEM_BYTES>>>(a, WoT_l, bo + l * D_MOD, o,
                                                     S_LEN, D_MOD, D_MOD, 0);
        ln_kernel<<<S_LEN, 256>>>(x, o, ln1_g + l * D_MOD, ln1_b + l * D_MOD, xr);

        tgemm_kernel<<<tg3072, 256, TGH_SMEM_BYTES>>>(xr, f1T_l, bff1 + l * FF_DIM, ff,
                                                      S_LEN, FF_DIM, D_MOD, 2);
        tgemm_kernel<<<tg768, 256, TGH_SMEM_BYTES>>>(ff, f2T_l, bff2 + l * D_MOD, o,
                                                     S_LEN, D_MOD, FF_DIM, 0);
        ln_kernel<<<S_LEN, 256>>>(x, o, ln2_g + l * D_MOD, ln2_b + l * D_MOD, xr);
    }

    zero_pooled_kernel<<<1, 256>>>(pooled);
    msum_kernel<<<1, 256>>>(mask, msum);
    pool_kernel<<<S_LEN / 256, 256>>>(x, mask, pooled);
    head1_kernel<<<1, 512>>>(pooled, W1, b1, msum, h1);
    head2_kernel<<<1, 256>>>(h1, W2, b2, h2);
    head3_kernel<<<1, 256>>>(h2, W3, b3, out, out_size);
}